// round 10
// baseline (speedup 1.0000x reference)
#include <cuda_runtime.h>
#include <cuda_bf16.h>
#include <math.h>

#define B_   2
#define T_   8192
#define H_   16
#define KD   32
#define VD   64
#define BT_  64
#define NT_  128
#define NCHUNK 4096   // B*H*NT

typedef unsigned long long ull;

__device__ __forceinline__ void fma2(ull& acc, ull a, ull b) {
    asm("fma.rn.f32x2 %0, %1, %2, %3;" : "=l"(acc) : "l"(a), "l"(b), "l"(acc));
}
__device__ __forceinline__ ull dup2(float x) {
    ull r; asm("mov.b64 %0, {%1, %2};" : "=l"(r) : "f"(x), "f"(x)); return r;
}
__device__ __forceinline__ float2 unpack2(ull v) {
    float2 r; asm("mov.b64 {%0, %1}, %2;" : "=f"(r.x), "=f"(r.y) : "l"(v)); return r;
}

// ---------------- tf32x3 mma helpers (m16n8k8) ----------------
__device__ __forceinline__ unsigned f2tf(float x) {
    unsigned r; asm("cvt.rna.tf32.f32 %0, %1;" : "=r"(r) : "f"(x)); return r;
}
__device__ __forceinline__ void split_tf(float x, unsigned& hi, unsigned& lo) {
    hi = f2tf(x);
    lo = f2tf(x - __uint_as_float(hi));
}
__device__ __forceinline__ void mma_m16n8k8(float c[4], const unsigned a[4], const unsigned b[2]) {
    asm volatile("mma.sync.aligned.m16n8k8.row.col.f32.tf32.tf32.f32 "
        "{%0,%1,%2,%3}, {%4,%5,%6,%7}, {%8,%9}, {%0,%1,%2,%3};"
        : "+f"(c[0]), "+f"(c[1]), "+f"(c[2]), "+f"(c[3])
        : "r"(a[0]), "r"(a[1]), "r"(a[2]), "r"(a[3]), "r"(b[0]), "r"(b[1]));
}
__device__ __forceinline__ void mma3(float c[4], const unsigned ahi[4], const unsigned alo[4],
                                     const unsigned bhi[2], const unsigned blo[2]) {
    mma_m16n8k8(c, ahi, bhi);
    mma_m16n8k8(c, ahi, blo);
    mma_m16n8k8(c, alo, bhi);
}
// A row-major fragment at (rows row,row+8; cols col,col+4)
__device__ __forceinline__ void loadA_frag(const float* A, int ld, int row, int col,
                                           unsigned hi[4], unsigned lo[4], float sgn) {
    float v0 = sgn * A[row*ld + col];
    float v1 = sgn * A[(row+8)*ld + col];
    float v2 = sgn * A[row*ld + col + 4];
    float v3 = sgn * A[(row+8)*ld + col + 4];
    split_tf(v0, hi[0], lo[0]); split_tf(v1, hi[1], lo[1]);
    split_tf(v2, hi[2], lo[2]); split_tf(v3, hi[3], lo[3]);
}
// B fragment from NT storage (B[n][k] row-major over n)
__device__ __forceinline__ void loadB_nt(const float* Bm, int ld, int nrow, int kcol,
                                         unsigned hi[2], unsigned lo[2]) {
    split_tf(Bm[nrow*ld + kcol],     hi[0], lo[0]);
    split_tf(Bm[nrow*ld + kcol + 4], hi[1], lo[1]);
}
// B fragment from KN storage (B[k][n] row-major over k)
__device__ __forceinline__ void loadB_kn(const float* Bm, int ld, int krow, int ncol,
                                         unsigned hi[2], unsigned lo[2]) {
    split_tf(Bm[krow*ld + ncol],       hi[0], lo[0]);
    split_tf(Bm[(krow+4)*ld + ncol],   hi[1], lo[1]);
}

// ------------------- device scratch (no allocation allowed) ---------------
__device__ float g_P [NCHUNK*KD*KD];
__device__ float g_C [NCHUNK*KD*VD];
__device__ float g_E [NCHUNK*KD];
__device__ float g_W [NCHUNK*BT_*KD];
__device__ float g_U [(size_t)NCHUNK*BT_*VD];
__device__ float g_QG[NCHUNK*BT_*KD];
__device__ float g_KD[NCHUNK*BT_*KD];           // kdR row-major [64][32]
__device__ float g_S [(size_t)NCHUNK*KD*VD];

// ---------------- phase-1 smem layout (floats) ----------------
#define P1_KQ   0        // b*kg [64][36]
#define P1_KD   2304     // kdR  [64][36]
#define P1_V    4608     // b*v [64][64]; gcum overlays [64][32]
#define P1_L    8704     // L [64][68]
#define P1_B    13056    // beta [64]
#define P1_E    13120    // e [32]
#define P1_BS   13152    // block sums [8][32]
#define P1_FLOATS 13408
#define P1_BYTES  (P1_FLOATS*4)      // 53632

// ---------------- phase-3 smem layout (floats) ----------------
#define P3_A    0        // Aqk [64][68]
#define P3_KD2  4352     // kdR [64][36]; later S [32][72]
#define P3_WQ   6656     // qg then w [64][36]
#define P3_VN   8960     // u -> v_new [64][72]
#define P3_FLOATS 13568
#define P3_BYTES  (P3_FLOATS*4)      // 54272

// ===========================================================================
__global__ void __launch_bounds__(256, 4) phase1_kernel(
    const float* __restrict__ q, const float* __restrict__ k,
    const float* __restrict__ v, const float* __restrict__ graw,
    const float* __restrict__ beta, const float* __restrict__ A_log,
    const float* __restrict__ dt_bias)
{
    extern __shared__ float sm[];
    float* sKQ = sm + P1_KQ;    // stride 36
    float* sKD = sm + P1_KD;    // stride 36
    float* sV  = sm + P1_V;     // stride 64
    float* sG  = sm + P1_V;     // overlay [64][32]
    float* sL  = sm + P1_L;     // stride 68
    float* sB  = sm + P1_B;
    float* sE  = sm + P1_E;
    float* sBS = sm + P1_BS;

    const int cid  = blockIdx.x;
    const int pair = cid >> 7, c = cid & 127;
    const int b    = pair >> 4, h = pair & 15;
    const int t0   = c * BT_;
    const int tid  = threadIdx.x;
    const int warp = tid >> 5, lane = tid & 31;
    const int gid  = lane >> 2, tg = lane & 3;
    const int m0   = (warp >> 1) << 4;
    const int n0   = (warp & 1) << 5;

    const float expA = __expf(A_log[h]);

    // ---- gate ----
    for (int idx = tid; idx < 512; idx += 256) {
        int i = idx >> 3, q4 = (idx & 7) << 2;
        float4 gr = *(const float4*)(graw + (((size_t)(b*T_ + t0 + i)*H_ + h) << 5) + q4);
        float4 db = *(const float4*)(dt_bias + h*KD + q4);
        float4 o;
        o.x = -expA*(fmaxf(gr.x+db.x,0.f) + log1pf(__expf(-fabsf(gr.x+db.x))));
        o.y = -expA*(fmaxf(gr.y+db.y,0.f) + log1pf(__expf(-fabsf(gr.y+db.y))));
        o.z = -expA*(fmaxf(gr.z+db.z,0.f) + log1pf(__expf(-fabsf(gr.z+db.z))));
        o.w = -expA*(fmaxf(gr.w+db.w,0.f) + log1pf(__expf(-fabsf(gr.w+db.w))));
        *(float4*)(sG + i*KD + q4) = o;
    }
    for (int i = tid; i < BT_; i += 256)
        sB[i] = beta[(size_t)(b*T_ + t0 + i)*H_ + h];
    __syncthreads();

    // ---- parallel cumsum ----
    {
        const int blk = tid >> 5, kk = tid & 31;
        float pref[8];
        float run = 0.f;
        #pragma unroll
        for (int t = 0; t < 8; t++) {
            run += sG[(blk*8 + t)*KD + kk];
            pref[t] = run;
        }
        sBS[blk*32 + kk] = run;
        __syncthreads();
        float pre = 0.f;
        #pragma unroll
        for (int j = 0; j < 7; j++)
            if (j < blk) pre += sBS[j*32 + kk];
        #pragma unroll
        for (int t = 0; t < 8; t++)
            sG[(blk*8 + t)*KD + kk] = fmaxf(pre + pref[t], -80.f);
        if (blk == 7) sE[kk] = __expf(fmaxf(pre + pref[7], -80.f));
    }
    __syncthreads();

    // ---- k,q rows: b*kg -> sKQ, kdR -> sKD, qg -> g_QG ----
    for (int r = warp; r < BT_; r += 8) {
        float gc = sG[r*KD + lane];
        float eg = __expf(gc);

        float kv = k[((size_t)((b*T_+t0+r)*H_ + h) << 5) + lane];
        float ss = kv*kv;
        #pragma unroll
        for (int o = 16; o; o >>= 1) ss += __shfl_xor_sync(0xffffffffu, ss, o);
        float kn = kv / fmaxf(sqrtf(ss), 1e-6f);
        sKQ[r*36 + lane] = sB[r] * kn * eg;
        sKD[r*36 + lane] = kn * __expf(-gc);

        float qv = q[((size_t)((b*T_+t0+r)*H_+h) << 5) + lane];
        float qs = qv*qv;
        #pragma unroll
        for (int o = 16; o; o >>= 1) qs += __shfl_xor_sync(0xffffffffu, qs, o);
        float qn = 0.1767766952966369f * qv / fmaxf(sqrtf(qs), 1e-6f);
        g_QG[(size_t)cid*2048 + r*KD + lane] = qn * eg;
    }
    __syncthreads();   // sG dead

    // ---- b*v -> sV ----
    for (int idx = tid; idx < 1024; idx += 256) {
        int i = idx >> 4, c4 = (idx & 15) << 2;
        float4 vv = *(const float4*)(v + (((size_t)(b*T_+t0+i)*H_+h) << 6) + c4);
        float bi = sB[i];
        vv.x *= bi; vv.y *= bi; vv.z *= bi; vv.w *= bi;
        *(float4*)(sV + i*64 + c4) = vv;
    }

    // ---- L = (b*kg) @ kdR^T via tf32x3 mma ----
    {
        float lac[4][4];
        #pragma unroll
        for (int nt = 0; nt < 4; nt++)
            #pragma unroll
            for (int r = 0; r < 4; r++) lac[nt][r] = 0.f;
        #pragma unroll
        for (int kt = 0; kt < 4; kt++) {
            const int k0 = kt << 3;
            unsigned ahi[4], alo[4];
            loadA_frag(sKQ, 36, m0 + gid, k0 + tg, ahi, alo, 1.f);
            #pragma unroll
            for (int nt = 0; nt < 4; nt++) {
                unsigned bhi[2], blo[2];
                loadB_nt(sKD, 36, n0 + nt*8 + gid, k0 + tg, bhi, blo);
                mma3(lac[nt], ahi, alo, bhi, blo);
            }
        }
        #pragma unroll
        for (int nt = 0; nt < 4; nt++) {
            const int cb = n0 + nt*8 + 2*tg;
            sL[(m0+gid)*68 + cb]     = lac[nt][0];
            sL[(m0+gid)*68 + cb + 1] = lac[nt][1];
            sL[(m0+gid+8)*68 + cb]     = lac[nt][2];
            sL[(m0+gid+8)*68 + cb + 1] = lac[nt][3];
        }
    }
    __syncthreads();

    // ---- blocked forward substitution on x = [sKQ(36) | sV(64)] ----
    #pragma unroll 1
    for (int blk = 0; blk < 4; ++blk) {
        const int r0 = blk << 4;
        if (blk) {
            if (tid < 96) {
                const int rg = tid & 3, cgs = tid >> 2;
                float* xb; int strd, xc;
                if (cgs < 8) { xb = sKQ; strd = 36; xc = cgs << 2; }
                else         { xb = sV;  strd = 64; xc = (cgs - 8) << 2; }
                const int rb = r0 + (rg << 2);
                ull acc[8];
                #pragma unroll
                for (int r = 0; r < 4; r++) {
                    ulonglong2 u2 = *(const ulonglong2*)(xb + (rb+r)*strd + xc);
                    acc[r*2] = u2.x; acc[r*2+1] = u2.y;
                }
                #pragma unroll 1
                for (int kx = 0; kx < r0; kx += 4) {
                    float Lv[4][4];
                    #pragma unroll
                    for (int r = 0; r < 4; r++)
                        *(float4*)Lv[r] = *(const float4*)(sL + (rb+r)*68 + kx);
                    #pragma unroll
                    for (int t = 0; t < 4; t++) {
                        ulonglong2 bv = *(const ulonglong2*)(xb + (kx+t)*strd + xc);
                        #pragma unroll
                        for (int r = 0; r < 4; r++) {
                            ull a = dup2(-Lv[r][t]);
                            fma2(acc[r*2], a, bv.x); fma2(acc[r*2+1], a, bv.y);
                        }
                    }
                }
                #pragma unroll
                for (int r = 0; r < 4; r++) {
                    ulonglong2 u2; u2.x = acc[r*2]; u2.y = acc[r*2+1];
                    *(ulonglong2*)(xb + (rb+r)*strd + xc) = u2;
                }
            }
            __syncthreads();
        }
        if (tid < 96) {
            float xr[16];
            if (tid < 32) {
                #pragma unroll
                for (int i = 0; i < 16; i++) xr[i] = sKQ[(r0+i)*36 + tid];
            } else {
                const int cc = tid - 32;
                #pragma unroll
                for (int i = 0; i < 16; i++) xr[i] = sV[(r0+i)*64 + cc];
            }
            #pragma unroll
            for (int i = 1; i < 16; i++) {
                const float* Lr = sL + (r0+i)*68 + r0;
                #pragma unroll
                for (int j = 0; j < i; j++)
                    xr[i] = fmaf(-Lr[j], xr[j], xr[i]);
            }
            if (tid < 32) {
                #pragma unroll
                for (int i = 1; i < 16; i++) sKQ[(r0+i)*36 + tid] = xr[i];
            } else {
                const int cc = tid - 32;
                #pragma unroll
                for (int i = 1; i < 16; i++) sV[(r0+i)*64 + cc] = xr[i];
            }
        }
        __syncthreads();
    }
    // w in sKQ, u in sV

    // ---- fused P|C = e * (kdR^T @ [w|u]) ----
    if (tid < 192) {
        const int kkg = tid & 7, cg = tid >> 3;
        const int kk0 = kkg << 2;
        float* xb; int strd, xc;
        if (cg < 8) { xb = sKQ; strd = 36; xc = cg << 2; }
        else        { xb = sV;  strd = 64; xc = (cg - 8) << 2; }
        ull acc[8];
        #pragma unroll
        for (int r = 0; r < 8; r++) acc[r] = 0ull;
        #pragma unroll 4
        for (int i = 0; i < BT_; i++) {
            float a4[4];
            *(float4*)a4 = *(const float4*)(sKD + i*36 + kk0);
            ulonglong2 bv = *(const ulonglong2*)(xb + i*strd + xc);
            #pragma unroll
            for (int r = 0; r < 4; r++) {
                ull ad = dup2(a4[r]);
                fma2(acc[r*2], ad, bv.x); fma2(acc[r*2+1], ad, bv.y);
            }
        }
        #pragma unroll
        for (int r = 0; r < 4; r++) {
            float e = sE[kk0 + r];
            float2 p0 = unpack2(acc[r*2]), p1 = unpack2(acc[r*2+1]);
            float4 val = make_float4(e*p0.x, e*p0.y, e*p1.x, e*p1.y);
            if (cg < 8)
                *(float4*)(g_P + (size_t)cid*1024 + (kk0+r)*32 + (cg<<2)) = val;
            else
                *(float4*)(g_C + (size_t)cid*2048 + (kk0+r)*64 + ((cg-8)<<2)) = val;
        }
    }
    if (tid < KD) g_E[cid*KD + tid] = sE[tid];

    // ---- store w, u, kdR ----
    for (int idx = tid; idx < 512; idx += 256) {
        int i = idx >> 3, c4 = (idx & 7) << 2;
        *(float4*)(g_W + (size_t)cid*2048 + i*32 + c4) =
            *(const float4*)(sKQ + i*36 + c4);
    }
    for (int idx = tid; idx < 1024; idx += 256) {
        int i = idx >> 4, c4 = (idx & 15) << 2;
        *(float4*)(g_U + (size_t)cid*4096 + i*64 + c4) =
            *(const float4*)(sV + i*64 + c4);
    }
    for (int idx = tid; idx < 512; idx += 256) {
        int i = idx >> 3, c4 = (idx & 7) << 2;
        *(float4*)(g_KD + (size_t)cid*2048 + i*32 + c4) =
            *(const float4*)(sKD + i*36 + c4);
    }
}

// ===========================================================================
// Phase 2: S_{t+1} = diag(e)S - P S + C.  1 warp per (pair, 8-col slice).
// ===========================================================================
#define P4C(arr, m) ( ((m)&3)==0 ? arr[(m)>>2].x : ((m)&3)==1 ? arr[(m)>>2].y \
                    : ((m)&3)==2 ? arr[(m)>>2].z : arr[(m)>>2].w )

__global__ void __launch_bounds__(32) phase2_kernel()
{
    const int p     = blockIdx.x >> 3;
    const int vbase = (blockIdx.x & 7) << 3;
    const int lane  = threadIdx.x;
    const size_t base = (size_t)p*128;

    float4 Pc[8], Pn[8], Cc[2], Cn[2];
    float  ec, en;
    float  s[8];
    #pragma unroll
    for (int j = 0; j < 8; j++) s[j] = 0.f;

    {
        const float4* Pp = (const float4*)(g_P + base*1024 + lane*32);
        #pragma unroll
        for (int r = 0; r < 8; r++) Pc[r] = Pp[r];
        const float4* Cp = (const float4*)(g_C + base*2048 + lane*64 + vbase);
        Cc[0] = Cp[0]; Cc[1] = Cp[1];
        ec = g_E[base*32 + lane];
    }

    #pragma unroll 1
    for (int t = 0; t < 128; t++) {
        const size_t cid = base + t;
        if (t + 1 < 128) {
            const size_t cid1 = cid + 1;
            const float4* Pp = (const float4*)(g_P + cid1*1024 + lane*32);
            #pragma unroll
            for (int r = 0; r < 8; r++) Pn[r] = Pp[r];
            const float4* Cp = (const float4*)(g_C + cid1*2048 + lane*64 + vbase);
            Cn[0] = Cp[0]; Cn[1] = Cp[1];
            en = g_E[cid1*32 + lane];
        }
        float4* Sp = (float4*)(g_S + cid*2048 + lane*64 + vbase);
        Sp[0] = make_float4(s[0], s[1], s[2], s[3]);
        Sp[1] = make_float4(s[4], s[5], s[6], s[7]);

        float acc[8];
        acc[0]=fmaf(ec,s[0],Cc[0].x); acc[1]=fmaf(ec,s[1],Cc[0].y);
        acc[2]=fmaf(ec,s[2],Cc[0].z); acc[3]=fmaf(ec,s[3],Cc[0].w);
        acc[4]=fmaf(ec,s[4],Cc[1].x); acc[5]=fmaf(ec,s[5],Cc[1].y);
        acc[6]=fmaf(ec,s[6],Cc[1].z); acc[7]=fmaf(ec,s[7],Cc[1].w);

        #pragma unroll
        for (int m = 0; m < 32; m++) {
            float pm = P4C(Pc, m);
            #pragma unroll
            for (int j = 0; j < 8; j++)
                acc[j] = fmaf(-pm, __shfl_sync(0xffffffffu, s[j], m), acc[j]);
        }
        #pragma unroll
        for (int j = 0; j < 8; j++) s[j] = acc[j];
        #pragma unroll
        for (int r = 0; r < 8; r++) Pc[r] = Pn[r];
        Cc[0] = Cn[0]; Cc[1] = Cn[1];
        ec = en;
    }
}

// ===========================================================================
// Phase 3: o = qg S + Aqk (u - w S) — all GEMMs via tf32x3 mma
// ===========================================================================
__global__ void __launch_bounds__(256, 4) phase3_kernel(float* __restrict__ out)
{
    extern __shared__ float sm[];
    float* sA  = sm + P3_A;     // Aqk [64][68]
    float* sKD = sm + P3_KD2;   // kdR [64][36]
    float* sS  = sm + P3_KD2;   // S [32][72] (overlays kdR after GEMM1)
    float* sWQ = sm + P3_WQ;    // qg then w [64][36]
    float* sVn = sm + P3_VN;    // u -> v_new [64][72]

    const int cid  = blockIdx.x;
    const int pair = cid >> 7, c = cid & 127;
    const int b    = pair >> 4, h = pair & 15;
    const int t0   = c * BT_;
    const int tid  = threadIdx.x;
    const int warp = tid >> 5, lane = tid & 31;
    const int gid  = lane >> 2, tg = lane & 3;
    const int m0   = (warp >> 1) << 4;
    const int n0   = (warp & 1) << 5;

    // ---- load qg, kdR, u ----
    for (int idx = tid; idx < 512; idx += 256) {
        int i = idx >> 3, c4 = (idx & 7) << 2;
        *(float4*)(sWQ + i*36 + c4) =
            *(const float4*)(g_QG + (size_t)cid*2048 + i*32 + c4);
    }
    for (int idx = tid; idx < 512; idx += 256) {
        int i = idx >> 3, c4 = (idx & 7) << 2;
        *(float4*)(sKD + i*36 + c4) =
            *(const float4*)(g_KD + (size_t)cid*2048 + i*32 + c4);
    }
    for (int idx = tid; idx < 1024; idx += 256) {
        int i = idx >> 4, c4 = (idx & 15) << 2;
        *(float4*)(sVn + i*72 + c4) =
            *(const float4*)(g_U + (size_t)cid*4096 + i*64 + c4);
    }
    __syncthreads();

    // ---- GEMM1: Aqk = qg @ kdR^T -> sA ----
    {
        float aq[4][4];
        #pragma unroll
        for (int nt = 0; nt < 4; nt++)
            #pragma unroll
            for (int r = 0; r < 4; r++) aq[nt][r] = 0.f;
        #pragma unroll
        for (int kt = 0; kt < 4; kt++) {
            const int k0 = kt << 3;
            unsigned ahi[4], alo[4];
            loadA_frag(sWQ, 36, m0 + gid, k0 + tg, ahi, alo, 1.f);
            #pragma unroll
            for (int nt = 0; nt < 4; nt++) {
                unsigned bhi[2], blo[2];
                loadB_nt(sKD, 36, n0 + nt*8 + gid, k0 + tg, bhi, blo);
                mma3(aq[nt], ahi, alo, bhi, blo);
            }
        }
        #pragma unroll
        for (int nt = 0; nt < 4; nt++) {
            const int cb = n0 + nt*8 + 2*tg;
            sA[(m0+gid)*68 + cb]       = aq[nt][0];
            sA[(m0+gid)*68 + cb + 1]   = aq[nt][1];
            sA[(m0+gid+8)*68 + cb]     = aq[nt][2];
            sA[(m0+gid+8)*68 + cb + 1] = aq[nt][3];
        }
    }
    __syncthreads();   // kdR dead; Aqk visible

    // ---- load S over kdR region [32][72] ----
    for (int idx = tid; idx < 512; idx += 256) {
        int kk = idx >> 4, c4 = (idx & 15) << 2;
        *(float4*)(sS + kk*72 + c4) =
            *(const float4*)(g_S + (size_t)cid*2048 + kk*64 + c4);
    }
    __syncthreads();

    // ---- GEMM2: oacc = qg @ S ----
    float oac[4][4];
    #pragma unroll
    for (int nt = 0; nt < 4; nt++)
        #pragma unroll
        for (int r = 0; r < 4; r++) oac[nt][r] = 0.f;
    #pragma unroll
    for (int kt = 0; kt < 4; kt++) {
        const int k0 = kt << 3;
        unsigned ahi[4], alo[4];
        loadA_frag(sWQ, 36, m0 + gid, k0 + tg, ahi, alo, 1.f);
        #pragma unroll
        for (int nt = 0; nt < 4; nt++) {
            unsigned bhi[2], blo[2];
            loadB_kn(sS, 72, k0 + tg, n0 + nt*8 + gid, bhi, blo);
            mma3(oac[nt], ahi, alo, bhi, blo);
        }
    }
    __syncthreads();   // qg dead

    // ---- load w over qg ----
    for (int idx = tid; idx < 512; idx += 256) {
        int i = idx >> 3, c4 = (idx & 7) << 2;
        *(float4*)(sWQ + i*36 + c4) =
            *(const float4*)(g_W + (size_t)cid*2048 + i*32 + c4);
    }
    __syncthreads();

    // ---- GEMM3: v_new = u + (-w) @ S, RMW into sVn ----
    {
        float ws[4][4];
        #pragma unroll
        for (int nt = 0; nt < 4; nt++)
            #pragma unroll
            for (int r = 0; r < 4; r++) ws[nt][r] = 0.f;
        #pragma unroll
        for (int kt = 0; kt < 4; kt++) {
            const int k0 = kt << 3;
            unsigned ahi[4], alo[4];
            loadA_frag(sWQ, 36, m0 + gid, k0 + tg, ahi, alo, -1.f);
            #pragma unroll
            for (int nt = 0; nt < 4; nt++) {
                unsigned bhi[2], blo[2];
                loadB_kn(sS, 72, k0 + tg, n0 + nt*8 + gid, bhi, blo);
                mma3(ws[nt], ahi, alo, bhi, blo);
            }
        }
        #pragma unroll
        for (int nt = 0; nt < 4; nt++) {
            const int cb = n0 + nt*8 + 2*tg;
            sVn[(m0+gid)*72 + cb]       += ws[nt][0];
            sVn[(m0+gid)*72 + cb + 1]   += ws[nt][1];
            sVn[(m0+gid+8)*72 + cb]     += ws[nt][2];
            sVn[(m0+gid+8)*72 + cb + 1] += ws[nt][3];
        }
    }
    __syncthreads();

    // ---- GEMM5: oacc += tril(Aqk) @ v_new ----
    {
        const int ktmax = (m0 + 15) >> 3;   // 1,3,5,7 per warpM
        #pragma unroll 2
        for (int kt = 0; kt <= ktmax; kt++) {
            const int k0 = kt << 3;
            const int r0i = m0 + gid, r1i = m0 + gid + 8;
            float v0 = (k0 + tg     <= r0i) ? sA[r0i*68 + k0 + tg]     : 0.f;
            float v1 = (k0 + tg     <= r1i) ? sA[r1i*68 + k0 + tg]     : 0.f;
            float v2 = (k0 + tg + 4 <= r0i) ? sA[r0i*68 + k0 + tg + 4] : 0.f;
            float v3 = (k0 + tg + 4 <= r1i) ? sA[r1i*68 + k0 + tg + 4] : 0.f;
            unsigned ahi[4], alo[4];
            split_tf(v0, ahi[0], alo[0]); split_tf(v1, ahi[1], alo[1]);
            split_tf(v2, ahi[2], alo[2]); split_tf(v3, ahi[3], alo[3]);
            #pragma unroll
            for (int nt = 0; nt < 4; nt++) {
                unsigned bhi[2], blo[2];
                loadB_kn(sVn, 72, k0 + tg, n0 + nt*8 + gid, bhi, blo);
                mma3(oac[nt], ahi, alo, bhi, blo);
            }
        }
    }

    // ---- store out from c-fragments ----
    #pragma unroll
    for (int nt = 0; nt < 4; nt++) {
        const int cb = n0 + nt*8 + 2*tg;
        const size_t r0o = (((size_t)(b*T_ + t0 + m0 + gid)*H_ + h) << 6);
        const size_t r1o = (((size_t)(b*T_ + t0 + m0 + gid + 8)*H_ + h) << 6);
        out[r0o + cb]     = oac[nt][0];
        out[r0o + cb + 1] = oac[nt][1];
        out[r1o + cb]     = oac[nt][2];
        out[r1o + cb + 1] = oac[nt][3];
    }
}

// ===========================================================================
extern "C" void kernel_launch(void* const* d_in, const int* in_sizes, int n_in,
                              void* d_out, int out_size)
{
    const float* q       = (const float*)d_in[0];
    const float* k       = (const float*)d_in[1];
    const float* v       = (const float*)d_in[2];
    const float* graw    = (const float*)d_in[3];
    const float* beta    = (const float*)d_in[4];
    const float* A_log   = (const float*)d_in[5];
    const float* dt_bias = (const float*)d_in[6];
    float* out = (float*)d_out;

    cudaFuncSetAttribute(phase1_kernel,
        cudaFuncAttributeMaxDynamicSharedMemorySize, P1_BYTES);
    cudaFuncSetAttribute(phase3_kernel,
        cudaFuncAttributeMaxDynamicSharedMemorySize, P3_BYTES);

    phase1_kernel<<<NCHUNK, 256, P1_BYTES>>>(q, k, v, graw, beta, A_log, dt_bias);
    phase2_kernel<<<256, 32>>>();
    phase3_kernel<<<NCHUNK, 256, P3_BYTES>>>(out);
}

// round 11
// speedup vs baseline: 1.0252x; 1.0252x over previous
#include <cuda_runtime.h>
#include <cuda_bf16.h>
#include <math.h>

#define B_   2
#define T_   8192
#define H_   16
#define KD   32
#define VD   64
#define BT_  64
#define NT_  128
#define NCHUNK 4096   // B*H*NT

typedef unsigned long long ull;

// ---------------- tf32x3 mma helpers (m16n8k8) ----------------
__device__ __forceinline__ unsigned f2tf(float x) {
    unsigned r; asm("cvt.rna.tf32.f32 %0, %1;" : "=r"(r) : "f"(x)); return r;
}
__device__ __forceinline__ void split_tf(float x, unsigned& hi, unsigned& lo) {
    hi = f2tf(x);
    lo = f2tf(x - __uint_as_float(hi));
}
__device__ __forceinline__ void mma_m16n8k8(float c[4], const unsigned a[4], const unsigned b[2]) {
    asm volatile("mma.sync.aligned.m16n8k8.row.col.f32.tf32.tf32.f32 "
        "{%0,%1,%2,%3}, {%4,%5,%6,%7}, {%8,%9}, {%0,%1,%2,%3};"
        : "+f"(c[0]), "+f"(c[1]), "+f"(c[2]), "+f"(c[3])
        : "r"(a[0]), "r"(a[1]), "r"(a[2]), "r"(a[3]), "r"(b[0]), "r"(b[1]));
}
__device__ __forceinline__ void mma3(float c[4], const unsigned ahi[4], const unsigned alo[4],
                                     const unsigned bhi[2], const unsigned blo[2]) {
    mma_m16n8k8(c, ahi, bhi);
    mma_m16n8k8(c, ahi, blo);
    mma_m16n8k8(c, alo, bhi);
}
// A row-major fragment at (rows row,row+8; cols col,col+4)
__device__ __forceinline__ void loadA_frag(const float* A, int ld, int row, int col,
                                           unsigned hi[4], unsigned lo[4], float sgn) {
    float v0 = sgn * A[row*ld + col];
    float v1 = sgn * A[(row+8)*ld + col];
    float v2 = sgn * A[row*ld + col + 4];
    float v3 = sgn * A[(row+8)*ld + col + 4];
    split_tf(v0, hi[0], lo[0]); split_tf(v1, hi[1], lo[1]);
    split_tf(v2, hi[2], lo[2]); split_tf(v3, hi[3], lo[3]);
}
// B fragment from NT storage (B[n][k] row-major over n)
__device__ __forceinline__ void loadB_nt(const float* Bm, int ld, int nrow, int kcol,
                                         unsigned hi[2], unsigned lo[2]) {
    split_tf(Bm[nrow*ld + kcol],     hi[0], lo[0]);
    split_tf(Bm[nrow*ld + kcol + 4], hi[1], lo[1]);
}
// B fragment from KN storage (B[k][n] row-major over k)
__device__ __forceinline__ void loadB_kn(const float* Bm, int ld, int krow, int ncol,
                                         unsigned hi[2], unsigned lo[2]) {
    split_tf(Bm[krow*ld + ncol],       hi[0], lo[0]);
    split_tf(Bm[(krow+4)*ld + ncol],   hi[1], lo[1]);
}

// ------------------- device scratch (no allocation allowed) ---------------
__device__ float g_P [NCHUNK*KD*KD];
__device__ float g_C [NCHUNK*KD*VD];
__device__ float g_E [NCHUNK*KD];
__device__ float g_W [NCHUNK*BT_*KD];
__device__ float g_U [(size_t)NCHUNK*BT_*VD];
__device__ float g_QG[NCHUNK*BT_*KD];
__device__ float g_KD[NCHUNK*BT_*KD];           // kdR row-major [64][32]
__device__ float g_S [(size_t)NCHUNK*KD*VD];

// ---------------- phase-1 smem layout (floats) ----------------
#define P1_KQ   0        // b*kg [64][36]
#define P1_KD   2304     // kdR  [64][36]
#define P1_V    4608     // b*v [64][64]; gcum overlays [64][32]
#define P1_L    8704     // L [64][68]
#define P1_B    13056    // beta [64]
#define P1_E    13120    // e [32]
#define P1_BS   13152    // block sums [8][32]
#define P1_FLOATS 13408
#define P1_BYTES  (P1_FLOATS*4)      // 53632

// ---------------- phase-3 smem layout (floats) ----------------
#define P3_A    0        // Aqk [64][68]
#define P3_KD2  4352     // kdR [64][36]; later S [32][72]
#define P3_WQ   6656     // qg then w [64][36]
#define P3_VN   8960     // u -> v_new [64][72]
#define P3_FLOATS 13568
#define P3_BYTES  (P3_FLOATS*4)      // 54272

// ===========================================================================
__global__ void __launch_bounds__(256, 4) phase1_kernel(
    const float* __restrict__ q, const float* __restrict__ k,
    const float* __restrict__ v, const float* __restrict__ graw,
    const float* __restrict__ beta, const float* __restrict__ A_log,
    const float* __restrict__ dt_bias)
{
    extern __shared__ float sm[];
    float* sKQ = sm + P1_KQ;    // stride 36
    float* sKD = sm + P1_KD;    // stride 36
    float* sV  = sm + P1_V;     // stride 64
    float* sG  = sm + P1_V;     // overlay [64][32]
    float* sL  = sm + P1_L;     // stride 68
    float* sB  = sm + P1_B;
    float* sE  = sm + P1_E;
    float* sBS = sm + P1_BS;

    const int cid  = blockIdx.x;
    const int pair = cid >> 7, c = cid & 127;
    const int b    = pair >> 4, h = pair & 15;
    const int t0   = c * BT_;
    const int tid  = threadIdx.x;
    const int warp = tid >> 5, lane = tid & 31;
    const int gid  = lane >> 2, tg = lane & 3;
    const int m0   = (warp >> 1) << 4;
    const int n0   = (warp & 1) << 5;

    const float expA = __expf(A_log[h]);

    // ---- gate ----
    for (int idx = tid; idx < 512; idx += 256) {
        int i = idx >> 3, q4 = (idx & 7) << 2;
        float4 gr = *(const float4*)(graw + (((size_t)(b*T_ + t0 + i)*H_ + h) << 5) + q4);
        float4 db = *(const float4*)(dt_bias + h*KD + q4);
        float4 o;
        o.x = -expA*(fmaxf(gr.x+db.x,0.f) + log1pf(__expf(-fabsf(gr.x+db.x))));
        o.y = -expA*(fmaxf(gr.y+db.y,0.f) + log1pf(__expf(-fabsf(gr.y+db.y))));
        o.z = -expA*(fmaxf(gr.z+db.z,0.f) + log1pf(__expf(-fabsf(gr.z+db.z))));
        o.w = -expA*(fmaxf(gr.w+db.w,0.f) + log1pf(__expf(-fabsf(gr.w+db.w))));
        *(float4*)(sG + i*KD + q4) = o;
    }
    for (int i = tid; i < BT_; i += 256)
        sB[i] = beta[(size_t)(b*T_ + t0 + i)*H_ + h];
    __syncthreads();

    // ---- parallel cumsum ----
    {
        const int blk = tid >> 5, kk = tid & 31;
        float pref[8];
        float run = 0.f;
        #pragma unroll
        for (int t = 0; t < 8; t++) {
            run += sG[(blk*8 + t)*KD + kk];
            pref[t] = run;
        }
        sBS[blk*32 + kk] = run;
        __syncthreads();
        float pre = 0.f;
        #pragma unroll
        for (int j = 0; j < 7; j++)
            if (j < blk) pre += sBS[j*32 + kk];
        #pragma unroll
        for (int t = 0; t < 8; t++)
            sG[(blk*8 + t)*KD + kk] = fmaxf(pre + pref[t], -80.f);
        if (blk == 7) sE[kk] = __expf(fmaxf(pre + pref[7], -80.f));
    }
    __syncthreads();

    // ---- k,q rows: b*kg -> sKQ, kdR -> sKD, qg -> g_QG ----
    for (int r = warp; r < BT_; r += 8) {
        float gc = sG[r*KD + lane];
        float eg = __expf(gc);

        float kv = k[((size_t)((b*T_+t0+r)*H_ + h) << 5) + lane];
        float ss = kv*kv;
        #pragma unroll
        for (int o = 16; o; o >>= 1) ss += __shfl_xor_sync(0xffffffffu, ss, o);
        float kn = kv / fmaxf(sqrtf(ss), 1e-6f);
        sKQ[r*36 + lane] = sB[r] * kn * eg;
        sKD[r*36 + lane] = kn * __expf(-gc);

        float qv = q[((size_t)((b*T_+t0+r)*H_+h) << 5) + lane];
        float qs = qv*qv;
        #pragma unroll
        for (int o = 16; o; o >>= 1) qs += __shfl_xor_sync(0xffffffffu, qs, o);
        float qn = 0.1767766952966369f * qv / fmaxf(sqrtf(qs), 1e-6f);
        g_QG[(size_t)cid*2048 + r*KD + lane] = qn * eg;
    }
    __syncthreads();   // sG dead

    // ---- b*v -> sV ----
    for (int idx = tid; idx < 1024; idx += 256) {
        int i = idx >> 4, c4 = (idx & 15) << 2;
        float4 vv = *(const float4*)(v + (((size_t)(b*T_+t0+i)*H_+h) << 6) + c4);
        float bi = sB[i];
        vv.x *= bi; vv.y *= bi; vv.z *= bi; vv.w *= bi;
        *(float4*)(sV + i*64 + c4) = vv;
    }

    // ---- L = (b*kg) @ kdR^T via tf32x3 mma (lower tiles only) ----
    if (n0 <= m0 + 15) {
        float lac[4][4];
        #pragma unroll
        for (int nt = 0; nt < 4; nt++)
            #pragma unroll
            for (int r = 0; r < 4; r++) lac[nt][r] = 0.f;
        #pragma unroll
        for (int kt = 0; kt < 4; kt++) {
            const int k0 = kt << 3;
            unsigned ahi[4], alo[4];
            loadA_frag(sKQ, 36, m0 + gid, k0 + tg, ahi, alo, 1.f);
            #pragma unroll
            for (int nt = 0; nt < 4; nt++) {
                if (n0 + nt*8 <= m0 + 15) {
                    unsigned bhi[2], blo[2];
                    loadB_nt(sKD, 36, n0 + nt*8 + gid, k0 + tg, bhi, blo);
                    mma3(lac[nt], ahi, alo, bhi, blo);
                }
            }
        }
        #pragma unroll
        for (int nt = 0; nt < 4; nt++) {
            if (n0 + nt*8 <= m0 + 15) {
                const int cb = n0 + nt*8 + 2*tg;
                sL[(m0+gid)*68 + cb]       = lac[nt][0];
                sL[(m0+gid)*68 + cb + 1]   = lac[nt][1];
                sL[(m0+gid+8)*68 + cb]     = lac[nt][2];
                sL[(m0+gid+8)*68 + cb + 1] = lac[nt][3];
            }
        }
    }
    __syncthreads();

    // ---- blocked forward substitution on x = [sKQ(36) | sV(64)] ----
    #pragma unroll 1
    for (int blk = 0; blk < 4; ++blk) {
        const int r0 = blk << 4;
        if (blk) {
            // panel update via tf32x3 mma: x[r0..r0+16) += (-L[r0..,0..r0)) @ x[0..r0)
            if (warp < 6) {
                const int n0w = warp << 4;
                const int ktn = blk << 1;     // r0/8
                float up[2][4];
                #pragma unroll
                for (int nt = 0; nt < 2; nt++)
                    #pragma unroll
                    for (int r = 0; r < 4; r++) up[nt][r] = 0.f;
                #pragma unroll 2
                for (int kt = 0; kt < ktn; kt++) {
                    const int k0 = kt << 3;
                    unsigned ahi[4], alo[4];
                    loadA_frag(sL, 68, r0 + gid, k0 + tg, ahi, alo, -1.f);
                    #pragma unroll
                    for (int nt = 0; nt < 2; nt++) {
                        const int ncol = n0w + nt*8;
                        const float* xb; int ld, off;
                        if (ncol < 32) { xb = sKQ; ld = 36; off = ncol; }
                        else           { xb = sV;  ld = 64; off = ncol - 32; }
                        unsigned bhi[2], blo[2];
                        loadB_kn(xb, ld, k0 + tg, off + gid, bhi, blo);
                        mma3(up[nt], ahi, alo, bhi, blo);
                    }
                }
                #pragma unroll
                for (int nt = 0; nt < 2; nt++) {
                    const int ncol = n0w + nt*8 + 2*tg;
                    float* xb; int ld, off;
                    if (ncol < 32) { xb = sKQ; ld = 36; off = ncol; }
                    else           { xb = sV;  ld = 64; off = ncol - 32; }
                    xb[(r0+gid)*ld + off]       += up[nt][0];
                    xb[(r0+gid)*ld + off + 1]   += up[nt][1];
                    xb[(r0+gid+8)*ld + off]     += up[nt][2];
                    xb[(r0+gid+8)*ld + off + 1] += up[nt][3];
                }
            }
            __syncthreads();
        }
        // in-block solve, columns in registers (96 threads)
        if (tid < 96) {
            float xr[16];
            if (tid < 32) {
                #pragma unroll
                for (int i = 0; i < 16; i++) xr[i] = sKQ[(r0+i)*36 + tid];
            } else {
                const int cc = tid - 32;
                #pragma unroll
                for (int i = 0; i < 16; i++) xr[i] = sV[(r0+i)*64 + cc];
            }
            #pragma unroll
            for (int i = 1; i < 16; i++) {
                const float* Lr = sL + (r0+i)*68 + r0;
                #pragma unroll
                for (int j = 0; j < i; j++)
                    xr[i] = fmaf(-Lr[j], xr[j], xr[i]);
            }
            if (tid < 32) {
                #pragma unroll
                for (int i = 1; i < 16; i++) sKQ[(r0+i)*36 + tid] = xr[i];
            } else {
                const int cc = tid - 32;
                #pragma unroll
                for (int i = 1; i < 16; i++) sV[(r0+i)*64 + cc] = xr[i];
            }
        }
        __syncthreads();
    }
    // w in sKQ, u in sV

    // ---- fused P|C = e * (kdR^T @ [w|u]) via tf32x3 mma ----
    // A = kd^T [32 x 64]: A[kk][i] = sKD[i*36+kk]; B = x [64 x 96]
    {
        const int wm = warp >> 2, wn = warp & 3;
        const int m0p = wm << 4;
        float pc[3][4];
        #pragma unroll
        for (int nt = 0; nt < 3; nt++)
            #pragma unroll
            for (int r = 0; r < 4; r++) pc[nt][r] = 0.f;
        #pragma unroll 2
        for (int kt = 0; kt < 8; kt++) {
            const int k0 = kt << 3;
            unsigned ahi[4], alo[4];
            {
                float v0 = sKD[(k0+tg)*36   + m0p + gid];
                float v1 = sKD[(k0+tg)*36   + m0p + gid + 8];
                float v2 = sKD[(k0+tg+4)*36 + m0p + gid];
                float v3 = sKD[(k0+tg+4)*36 + m0p + gid + 8];
                split_tf(v0, ahi[0], alo[0]); split_tf(v1, ahi[1], alo[1]);
                split_tf(v2, ahi[2], alo[2]); split_tf(v3, ahi[3], alo[3]);
            }
            #pragma unroll
            for (int nt = 0; nt < 3; nt++) {
                const int ncol = wn*24 + nt*8;
                const float* xb; int ld, off;
                if (ncol < 32) { xb = sKQ; ld = 36; off = ncol; }
                else           { xb = sV;  ld = 64; off = ncol - 32; }
                unsigned bhi[2], blo[2];
                loadB_kn(xb, ld, k0 + tg, off + gid, bhi, blo);
                mma3(pc[nt], ahi, alo, bhi, blo);
            }
        }
        #pragma unroll
        for (int nt = 0; nt < 3; nt++) {
            const int ncol = wn*24 + nt*8 + 2*tg;
            const int r0i = m0p + gid, r1i = m0p + gid + 8;
            float e0 = sE[r0i], e1 = sE[r1i];
            if (ncol < 32) {
                *(float2*)(g_P + (size_t)cid*1024 + r0i*32 + ncol) =
                    make_float2(e0*pc[nt][0], e0*pc[nt][1]);
                *(float2*)(g_P + (size_t)cid*1024 + r1i*32 + ncol) =
                    make_float2(e1*pc[nt][2], e1*pc[nt][3]);
            } else {
                *(float2*)(g_C + (size_t)cid*2048 + r0i*64 + (ncol-32)) =
                    make_float2(e0*pc[nt][0], e0*pc[nt][1]);
                *(float2*)(g_C + (size_t)cid*2048 + r1i*64 + (ncol-32)) =
                    make_float2(e1*pc[nt][2], e1*pc[nt][3]);
            }
        }
    }
    if (tid < KD) g_E[cid*KD + tid] = sE[tid];

    // ---- store w, u, kdR ----
    for (int idx = tid; idx < 512; idx += 256) {
        int i = idx >> 3, c4 = (idx & 7) << 2;
        *(float4*)(g_W + (size_t)cid*2048 + i*32 + c4) =
            *(const float4*)(sKQ + i*36 + c4);
    }
    for (int idx = tid; idx < 1024; idx += 256) {
        int i = idx >> 4, c4 = (idx & 15) << 2;
        *(float4*)(g_U + (size_t)cid*4096 + i*64 + c4) =
            *(const float4*)(sV + i*64 + c4);
    }
    for (int idx = tid; idx < 512; idx += 256) {
        int i = idx >> 3, c4 = (idx & 7) << 2;
        *(float4*)(g_KD + (size_t)cid*2048 + i*32 + c4) =
            *(const float4*)(sKD + i*36 + c4);
    }
}

// ===========================================================================
// Phase 2: S_{t+1} = diag(e)S - P S + C.  1 warp per (pair, 8-col slice).
// ===========================================================================
#define P4C(arr, m) ( ((m)&3)==0 ? arr[(m)>>2].x : ((m)&3)==1 ? arr[(m)>>2].y \
                    : ((m)&3)==2 ? arr[(m)>>2].z : arr[(m)>>2].w )

__global__ void __launch_bounds__(32) phase2_kernel()
{
    const int p     = blockIdx.x >> 3;
    const int vbase = (blockIdx.x & 7) << 3;
    const int lane  = threadIdx.x;
    const size_t base = (size_t)p*128;

    float4 Pc[8], Pn[8], Cc[2], Cn[2];
    float  ec, en;
    float  s[8];
    #pragma unroll
    for (int j = 0; j < 8; j++) s[j] = 0.f;

    {
        const float4* Pp = (const float4*)(g_P + base*1024 + lane*32);
        #pragma unroll
        for (int r = 0; r < 8; r++) Pc[r] = Pp[r];
        const float4* Cp = (const float4*)(g_C + base*2048 + lane*64 + vbase);
        Cc[0] = Cp[0]; Cc[1] = Cp[1];
        ec = g_E[base*32 + lane];
    }

    #pragma unroll 1
    for (int t = 0; t < 128; t++) {
        const size_t cid = base + t;
        if (t + 1 < 128) {
            const size_t cid1 = cid + 1;
            const float4* Pp = (const float4*)(g_P + cid1*1024 + lane*32);
            #pragma unroll
            for (int r = 0; r < 8; r++) Pn[r] = Pp[r];
            const float4* Cp = (const float4*)(g_C + cid1*2048 + lane*64 + vbase);
            Cn[0] = Cp[0]; Cn[1] = Cp[1];
            en = g_E[cid1*32 + lane];
        }
        float4* Sp = (float4*)(g_S + cid*2048 + lane*64 + vbase);
        Sp[0] = make_float4(s[0], s[1], s[2], s[3]);
        Sp[1] = make_float4(s[4], s[5], s[6], s[7]);

        float acc[8];
        acc[0]=fmaf(ec,s[0],Cc[0].x); acc[1]=fmaf(ec,s[1],Cc[0].y);
        acc[2]=fmaf(ec,s[2],Cc[0].z); acc[3]=fmaf(ec,s[3],Cc[0].w);
        acc[4]=fmaf(ec,s[4],Cc[1].x); acc[5]=fmaf(ec,s[5],Cc[1].y);
        acc[6]=fmaf(ec,s[6],Cc[1].z); acc[7]=fmaf(ec,s[7],Cc[1].w);

        #pragma unroll
        for (int m = 0; m < 32; m++) {
            float pm = P4C(Pc, m);
            #pragma unroll
            for (int j = 0; j < 8; j++)
                acc[j] = fmaf(-pm, __shfl_sync(0xffffffffu, s[j], m), acc[j]);
        }
        #pragma unroll
        for (int j = 0; j < 8; j++) s[j] = acc[j];
        #pragma unroll
        for (int r = 0; r < 8; r++) Pc[r] = Pn[r];
        Cc[0] = Cn[0]; Cc[1] = Cn[1];
        ec = en;
    }
}

// ===========================================================================
// Phase 3: o = qg S + Aqk (u - w S) — all GEMMs via tf32x3 mma
// ===========================================================================
__global__ void __launch_bounds__(256, 4) phase3_kernel(float* __restrict__ out)
{
    extern __shared__ float sm[];
    float* sA  = sm + P3_A;     // Aqk [64][68]
    float* sKD = sm + P3_KD2;   // kdR [64][36]
    float* sS  = sm + P3_KD2;   // S [32][72] (overlays kdR after GEMM1)
    float* sWQ = sm + P3_WQ;    // qg then w [64][36]
    float* sVn = sm + P3_VN;    // u -> v_new [64][72]

    const int cid  = blockIdx.x;
    const int pair = cid >> 7, c = cid & 127;
    const int b    = pair >> 4, h = pair & 15;
    const int t0   = c * BT_;
    const int tid  = threadIdx.x;
    const int warp = tid >> 5, lane = tid & 31;
    const int gid  = lane >> 2, tg = lane & 3;
    const int m0   = (warp >> 1) << 4;
    const int n0   = (warp & 1) << 5;

    // ---- load qg, kdR, u ----
    for (int idx = tid; idx < 512; idx += 256) {
        int i = idx >> 3, c4 = (idx & 7) << 2;
        *(float4*)(sWQ + i*36 + c4) =
            *(const float4*)(g_QG + (size_t)cid*2048 + i*32 + c4);
    }
    for (int idx = tid; idx < 512; idx += 256) {
        int i = idx >> 3, c4 = (idx & 7) << 2;
        *(float4*)(sKD + i*36 + c4) =
            *(const float4*)(g_KD + (size_t)cid*2048 + i*32 + c4);
    }
    for (int idx = tid; idx < 1024; idx += 256) {
        int i = idx >> 4, c4 = (idx & 15) << 2;
        *(float4*)(sVn + i*72 + c4) =
            *(const float4*)(g_U + (size_t)cid*4096 + i*64 + c4);
    }
    __syncthreads();

    // ---- GEMM1: Aqk = qg @ kdR^T -> sA (lower tiles only) ----
    if (n0 <= m0 + 15) {
        float aq[4][4];
        #pragma unroll
        for (int nt = 0; nt < 4; nt++)
            #pragma unroll
            for (int r = 0; r < 4; r++) aq[nt][r] = 0.f;
        #pragma unroll
        for (int kt = 0; kt < 4; kt++) {
            const int k0 = kt << 3;
            unsigned ahi[4], alo[4];
            loadA_frag(sWQ, 36, m0 + gid, k0 + tg, ahi, alo, 1.f);
            #pragma unroll
            for (int nt = 0; nt < 4; nt++) {
                if (n0 + nt*8 <= m0 + 15) {
                    unsigned bhi[2], blo[2];
                    loadB_nt(sKD, 36, n0 + nt*8 + gid, k0 + tg, bhi, blo);
                    mma3(aq[nt], ahi, alo, bhi, blo);
                }
            }
        }
        #pragma unroll
        for (int nt = 0; nt < 4; nt++) {
            if (n0 + nt*8 <= m0 + 15) {
                const int cb = n0 + nt*8 + 2*tg;
                sA[(m0+gid)*68 + cb]       = aq[nt][0];
                sA[(m0+gid)*68 + cb + 1]   = aq[nt][1];
                sA[(m0+gid+8)*68 + cb]     = aq[nt][2];
                sA[(m0+gid+8)*68 + cb + 1] = aq[nt][3];
            }
        }
    }
    __syncthreads();   // kdR dead; Aqk visible

    // ---- load S over kdR region [32][72] ----
    for (int idx = tid; idx < 512; idx += 256) {
        int kk = idx >> 4, c4 = (idx & 15) << 2;
        *(float4*)(sS + kk*72 + c4) =
            *(const float4*)(g_S + (size_t)cid*2048 + kk*64 + c4);
    }
    __syncthreads();

    // ---- GEMM2: oacc = qg @ S ----
    float oac[4][4];
    #pragma unroll
    for (int nt = 0; nt < 4; nt++)
        #pragma unroll
        for (int r = 0; r < 4; r++) oac[nt][r] = 0.f;
    #pragma unroll
    for (int kt = 0; kt < 4; kt++) {
        const int k0 = kt << 3;
        unsigned ahi[4], alo[4];
        loadA_frag(sWQ, 36, m0 + gid, k0 + tg, ahi, alo, 1.f);
        #pragma unroll
        for (int nt = 0; nt < 4; nt++) {
            unsigned bhi[2], blo[2];
            loadB_kn(sS, 72, k0 + tg, n0 + nt*8 + gid, bhi, blo);
            mma3(oac[nt], ahi, alo, bhi, blo);
        }
    }
    __syncthreads();   // qg dead

    // ---- load w over qg ----
    for (int idx = tid; idx < 512; idx += 256) {
        int i = idx >> 3, c4 = (idx & 7) << 2;
        *(float4*)(sWQ + i*36 + c4) =
            *(const float4*)(g_W + (size_t)cid*2048 + i*32 + c4);
    }
    __syncthreads();

    // ---- GEMM3: v_new = u + (-w) @ S, RMW into sVn ----
    {
        float ws[4][4];
        #pragma unroll
        for (int nt = 0; nt < 4; nt++)
            #pragma unroll
            for (int r = 0; r < 4; r++) ws[nt][r] = 0.f;
        #pragma unroll
        for (int kt = 0; kt < 4; kt++) {
            const int k0 = kt << 3;
            unsigned ahi[4], alo[4];
            loadA_frag(sWQ, 36, m0 + gid, k0 + tg, ahi, alo, -1.f);
            #pragma unroll
            for (int nt = 0; nt < 4; nt++) {
                unsigned bhi[2], blo[2];
                loadB_kn(sS, 72, k0 + tg, n0 + nt*8 + gid, bhi, blo);
                mma3(ws[nt], ahi, alo, bhi, blo);
            }
        }
        #pragma unroll
        for (int nt = 0; nt < 4; nt++) {
            const int cb = n0 + nt*8 + 2*tg;
            sVn[(m0+gid)*72 + cb]       += ws[nt][0];
            sVn[(m0+gid)*72 + cb + 1]   += ws[nt][1];
            sVn[(m0+gid+8)*72 + cb]     += ws[nt][2];
            sVn[(m0+gid+8)*72 + cb + 1] += ws[nt][3];
        }
    }
    __syncthreads();

    // ---- GEMM5: oacc += tril(Aqk) @ v_new ----
    {
        const int ktmax = (m0 + 15) >> 3;   // 1,3,5,7 per warpM
        #pragma unroll 2
        for (int kt = 0; kt <= ktmax; kt++) {
            const int k0 = kt << 3;
            const int r0i = m0 + gid, r1i = m0 + gid + 8;
            float v0 = (k0 + tg     <= r0i) ? sA[r0i*68 + k0 + tg]     : 0.f;
            float v1 = (k0 + tg     <= r1i) ? sA[r1i*68 + k0 + tg]     : 0.f;
            float v2 = (k0 + tg + 4 <= r0i) ? sA[r0i*68 + k0 + tg + 4] : 0.f;
            float v3 = (k0 + tg + 4 <= r1i) ? sA[r1i*68 + k0 + tg + 4] : 0.f;
            unsigned ahi[4], alo[4];
            split_tf(v0, ahi[0], alo[0]); split_tf(v1, ahi[1], alo[1]);
            split_tf(v2, ahi[2], alo[2]); split_tf(v3, ahi[3], alo[3]);
            #pragma unroll
            for (int nt = 0; nt < 4; nt++) {
                unsigned bhi[2], blo[2];
                loadB_kn(sVn, 72, k0 + tg, n0 + nt*8 + gid, bhi, blo);
                mma3(oac[nt], ahi, alo, bhi, blo);
            }
        }
    }

    // ---- store out from c-fragments ----
    #pragma unroll
    for (int nt = 0; nt < 4; nt++) {
        const int cb = n0 + nt*8 + 2*tg;
        const size_t r0o = (((size_t)(b*T_ + t0 + m0 + gid)*H_ + h) << 6);
        const size_t r1o = (((size_t)(b*T_ + t0 + m0 + gid + 8)*H_ + h) << 6);
        out[r0o + cb]     = oac[nt][0];
        out[r0o + cb + 1] = oac[nt][1];
        out[r1o + cb]     = oac[nt][2];
        out[r1o + cb + 1] = oac[nt][3];
    }
}

// ===========================================================================
extern "C" void kernel_launch(void* const* d_in, const int* in_sizes, int n_in,
                              void* d_out, int out_size)
{
    const float* q       = (const float*)d_in[0];
    const float* k       = (const float*)d_in[1];
    const float* v       = (const float*)d_in[2];
    const float* graw    = (const float*)d_in[3];
    const float* beta    = (const float*)d_in[4];
    const float* A_log   = (const float*)d_in[5];
    const float* dt_bias = (const float*)d_in[6];
    float* out = (float*)d_out;

    cudaFuncSetAttribute(phase1_kernel,
        cudaFuncAttributeMaxDynamicSharedMemorySize, P1_BYTES);
    cudaFuncSetAttribute(phase3_kernel,
        cudaFuncAttributeMaxDynamicSharedMemorySize, P3_BYTES);

    phase1_kernel<<<NCHUNK, 256, P1_BYTES>>>(q, k, v, graw, beta, A_log, dt_bias);
    phase2_kernel<<<256, 32>>>();
    phase3_kernel<<<NCHUNK, 256, P3_BYTES>>>(out);
}

// round 12
// speedup vs baseline: 1.1319x; 1.1041x over previous
#include <cuda_runtime.h>
#include <cuda_bf16.h>
#include <math.h>

#define B_   2
#define T_   8192
#define H_   16
#define KD   32
#define VD   64
#define BT_  64
#define NT_  128
#define NCHUNK 4096   // B*H*NT

typedef unsigned long long ull;

// ---------------- tf32x3 mma helpers (m16n8k8) ----------------
// Cheap split: hi = tf32-truncation of x (top 19 bits, exact), lo = x - hi
// (exact in fp32; the mma hardware truncates lo's low mantissa bits, leaving
// residual ~2^-21 relative -- far below the 1e-3 tolerance).
__device__ __forceinline__ void split_tf(float x, unsigned& hi, unsigned& lo) {
    hi = __float_as_uint(x) & 0xFFFFE000u;
    lo = __float_as_uint(x - __uint_as_float(hi));
}
__device__ __forceinline__ void mma_m16n8k8(float c[4], const unsigned a[4], const unsigned b[2]) {
    asm volatile("mma.sync.aligned.m16n8k8.row.col.f32.tf32.tf32.f32 "
        "{%0,%1,%2,%3}, {%4,%5,%6,%7}, {%8,%9}, {%0,%1,%2,%3};"
        : "+f"(c[0]), "+f"(c[1]), "+f"(c[2]), "+f"(c[3])
        : "r"(a[0]), "r"(a[1]), "r"(a[2]), "r"(a[3]), "r"(b[0]), "r"(b[1]));
}
__device__ __forceinline__ void mma3(float c[4], const unsigned ahi[4], const unsigned alo[4],
                                     const unsigned bhi[2], const unsigned blo[2]) {
    mma_m16n8k8(c, ahi, bhi);
    mma_m16n8k8(c, ahi, blo);
    mma_m16n8k8(c, alo, bhi);
}
// A row-major fragment at (rows row,row+8; cols col,col+4)
__device__ __forceinline__ void loadA_frag(const float* A, int ld, int row, int col,
                                           unsigned hi[4], unsigned lo[4], float sgn) {
    float v0 = sgn * A[row*ld + col];
    float v1 = sgn * A[(row+8)*ld + col];
    float v2 = sgn * A[row*ld + col + 4];
    float v3 = sgn * A[(row+8)*ld + col + 4];
    split_tf(v0, hi[0], lo[0]); split_tf(v1, hi[1], lo[1]);
    split_tf(v2, hi[2], lo[2]); split_tf(v3, hi[3], lo[3]);
}
// B fragment from NT storage (B[n][k] row-major over n)
__device__ __forceinline__ void loadB_nt(const float* Bm, int ld, int nrow, int kcol,
                                         unsigned hi[2], unsigned lo[2]) {
    split_tf(Bm[nrow*ld + kcol],     hi[0], lo[0]);
    split_tf(Bm[nrow*ld + kcol + 4], hi[1], lo[1]);
}
// B fragment from KN storage (B[k][n] row-major over k)
__device__ __forceinline__ void loadB_kn(const float* Bm, int ld, int krow, int ncol,
                                         unsigned hi[2], unsigned lo[2]) {
    split_tf(Bm[krow*ld + ncol],       hi[0], lo[0]);
    split_tf(Bm[(krow+4)*ld + ncol],   hi[1], lo[1]);
}
// fast softplus: abs error ~2^-24, fine after exp()
__device__ __forceinline__ float softplus_fast(float x) {
    return fmaxf(x, 0.f) + __logf(1.0f + __expf(-fabsf(x)));
}

// ------------------- device scratch (no allocation allowed) ---------------
__device__ float g_P [NCHUNK*KD*KD];
__device__ float g_C [NCHUNK*KD*VD];
__device__ float g_E [NCHUNK*KD];
__device__ float g_W [NCHUNK*BT_*KD];
__device__ float g_U [(size_t)NCHUNK*BT_*VD];
__device__ float g_QG[NCHUNK*BT_*KD];
__device__ float g_KD[NCHUNK*BT_*KD];           // kdR row-major [64][32]
__device__ float g_S [(size_t)NCHUNK*KD*VD];

// ---------------- phase-1 smem layout (floats) ----------------
#define P1_KQ   0        // b*kg [64][36]
#define P1_KD   2304     // kdR  [64][36]
#define P1_V    4608     // b*v [64][64]; gcum overlays [64][32]
#define P1_L    8704     // L [64][68]
#define P1_B    13056    // beta [64]
#define P1_E    13120    // e [32]
#define P1_BS   13152    // block sums [8][32]
#define P1_FLOATS 13408
#define P1_BYTES  (P1_FLOATS*4)      // 53632

// ---------------- phase-3 smem layout (floats) ----------------
#define P3_A    0        // Aqk [64][68]
#define P3_KD2  4352     // kdR [64][36]; later S [32][72]
#define P3_WQ   6656     // qg then w [64][36]
#define P3_VN   8960     // u -> v_new [64][72]
#define P3_FLOATS 13568
#define P3_BYTES  (P3_FLOATS*4)      // 54272

// ===========================================================================
__global__ void __launch_bounds__(256, 4) phase1_kernel(
    const float* __restrict__ q, const float* __restrict__ k,
    const float* __restrict__ v, const float* __restrict__ graw,
    const float* __restrict__ beta, const float* __restrict__ A_log,
    const float* __restrict__ dt_bias)
{
    extern __shared__ float sm[];
    float* sKQ = sm + P1_KQ;    // stride 36
    float* sKD = sm + P1_KD;    // stride 36
    float* sV  = sm + P1_V;     // stride 64
    float* sG  = sm + P1_V;     // overlay [64][32]
    float* sL  = sm + P1_L;     // stride 68
    float* sB  = sm + P1_B;
    float* sE  = sm + P1_E;
    float* sBS = sm + P1_BS;

    const int cid  = blockIdx.x;
    const int pair = cid >> 7, c = cid & 127;
    const int b    = pair >> 4, h = pair & 15;
    const int t0   = c * BT_;
    const int tid  = threadIdx.x;
    const int warp = tid >> 5, lane = tid & 31;
    const int gid  = lane >> 2, tg = lane & 3;
    const int m0   = (warp >> 1) << 4;
    const int n0   = (warp & 1) << 5;

    const float expA = __expf(A_log[h]);

    // ---- gate ----
    for (int idx = tid; idx < 512; idx += 256) {
        int i = idx >> 3, q4 = (idx & 7) << 2;
        float4 gr = *(const float4*)(graw + (((size_t)(b*T_ + t0 + i)*H_ + h) << 5) + q4);
        float4 db = *(const float4*)(dt_bias + h*KD + q4);
        float4 o;
        o.x = -expA * softplus_fast(gr.x + db.x);
        o.y = -expA * softplus_fast(gr.y + db.y);
        o.z = -expA * softplus_fast(gr.z + db.z);
        o.w = -expA * softplus_fast(gr.w + db.w);
        *(float4*)(sG + i*KD + q4) = o;
    }
    for (int i = tid; i < BT_; i += 256)
        sB[i] = beta[(size_t)(b*T_ + t0 + i)*H_ + h];
    __syncthreads();

    // ---- parallel cumsum ----
    {
        const int blk = tid >> 5, kk = tid & 31;
        float pref[8];
        float run = 0.f;
        #pragma unroll
        for (int t = 0; t < 8; t++) {
            run += sG[(blk*8 + t)*KD + kk];
            pref[t] = run;
        }
        sBS[blk*32 + kk] = run;
        __syncthreads();
        float pre = 0.f;
        #pragma unroll
        for (int j = 0; j < 7; j++)
            if (j < blk) pre += sBS[j*32 + kk];
        #pragma unroll
        for (int t = 0; t < 8; t++)
            sG[(blk*8 + t)*KD + kk] = fmaxf(pre + pref[t], -80.f);
        if (blk == 7) sE[kk] = __expf(fmaxf(pre + pref[7], -80.f));
    }
    __syncthreads();

    // ---- k,q rows: b*kg -> sKQ, kdR -> sKD, qg -> g_QG ----
    for (int r = warp; r < BT_; r += 8) {
        float gc = sG[r*KD + lane];
        float eg = __expf(gc);

        float kv = k[((size_t)((b*T_+t0+r)*H_ + h) << 5) + lane];
        float ss = kv*kv;
        #pragma unroll
        for (int o = 16; o; o >>= 1) ss += __shfl_xor_sync(0xffffffffu, ss, o);
        float kn = kv * rsqrtf(fmaxf(ss, 1e-12f));
        sKQ[r*36 + lane] = sB[r] * kn * eg;
        sKD[r*36 + lane] = kn * __expf(-gc);

        float qv = q[((size_t)((b*T_+t0+r)*H_+h) << 5) + lane];
        float qs = qv*qv;
        #pragma unroll
        for (int o = 16; o; o >>= 1) qs += __shfl_xor_sync(0xffffffffu, qs, o);
        float qn = 0.1767766952966369f * qv * rsqrtf(fmaxf(qs, 1e-12f));
        g_QG[(size_t)cid*2048 + r*KD + lane] = qn * eg;
    }
    __syncthreads();   // sG dead

    // ---- b*v -> sV ----
    for (int idx = tid; idx < 1024; idx += 256) {
        int i = idx >> 4, c4 = (idx & 15) << 2;
        float4 vv = *(const float4*)(v + (((size_t)(b*T_+t0+i)*H_+h) << 6) + c4);
        float bi = sB[i];
        vv.x *= bi; vv.y *= bi; vv.z *= bi; vv.w *= bi;
        *(float4*)(sV + i*64 + c4) = vv;
    }

    // ---- L = (b*kg) @ kdR^T via tf32x3 mma (lower tiles only) ----
    if (n0 <= m0 + 15) {
        float lac[4][4];
        #pragma unroll
        for (int nt = 0; nt < 4; nt++)
            #pragma unroll
            for (int r = 0; r < 4; r++) lac[nt][r] = 0.f;
        #pragma unroll
        for (int kt = 0; kt < 4; kt++) {
            const int k0 = kt << 3;
            unsigned ahi[4], alo[4];
            loadA_frag(sKQ, 36, m0 + gid, k0 + tg, ahi, alo, 1.f);
            #pragma unroll
            for (int nt = 0; nt < 4; nt++) {
                if (n0 + nt*8 <= m0 + 15) {
                    unsigned bhi[2], blo[2];
                    loadB_nt(sKD, 36, n0 + nt*8 + gid, k0 + tg, bhi, blo);
                    mma3(lac[nt], ahi, alo, bhi, blo);
                }
            }
        }
        #pragma unroll
        for (int nt = 0; nt < 4; nt++) {
            if (n0 + nt*8 <= m0 + 15) {
                const int cb = n0 + nt*8 + 2*tg;
                sL[(m0+gid)*68 + cb]       = lac[nt][0];
                sL[(m0+gid)*68 + cb + 1]   = lac[nt][1];
                sL[(m0+gid+8)*68 + cb]     = lac[nt][2];
                sL[(m0+gid+8)*68 + cb + 1] = lac[nt][3];
            }
        }
    }
    __syncthreads();

    // ---- blocked forward substitution on x = [sKQ(36) | sV(64)] ----
    #pragma unroll 1
    for (int blk = 0; blk < 4; ++blk) {
        const int r0 = blk << 4;
        if (blk) {
            // panel update via tf32x3 mma: x[r0..r0+16) += (-L[r0..,0..r0)) @ x[0..r0)
            if (warp < 6) {
                const int n0w = warp << 4;
                const int ktn = blk << 1;     // r0/8
                float up[2][4];
                #pragma unroll
                for (int nt = 0; nt < 2; nt++)
                    #pragma unroll
                    for (int r = 0; r < 4; r++) up[nt][r] = 0.f;
                #pragma unroll 2
                for (int kt = 0; kt < ktn; kt++) {
                    const int k0 = kt << 3;
                    unsigned ahi[4], alo[4];
                    loadA_frag(sL, 68, r0 + gid, k0 + tg, ahi, alo, -1.f);
                    #pragma unroll
                    for (int nt = 0; nt < 2; nt++) {
                        const int ncol = n0w + nt*8;
                        const float* xb; int ld, off;
                        if (ncol < 32) { xb = sKQ; ld = 36; off = ncol; }
                        else           { xb = sV;  ld = 64; off = ncol - 32; }
                        unsigned bhi[2], blo[2];
                        loadB_kn(xb, ld, k0 + tg, off + gid, bhi, blo);
                        mma3(up[nt], ahi, alo, bhi, blo);
                    }
                }
                #pragma unroll
                for (int nt = 0; nt < 2; nt++) {
                    const int ncol = n0w + nt*8 + 2*tg;
                    float* xb; int ld, off;
                    if (ncol < 32) { xb = sKQ; ld = 36; off = ncol; }
                    else           { xb = sV;  ld = 64; off = ncol - 32; }
                    xb[(r0+gid)*ld + off]       += up[nt][0];
                    xb[(r0+gid)*ld + off + 1]   += up[nt][1];
                    xb[(r0+gid+8)*ld + off]     += up[nt][2];
                    xb[(r0+gid+8)*ld + off + 1] += up[nt][3];
                }
            }
            __syncthreads();
        }
        // in-block solve, columns in registers (96 threads)
        if (tid < 96) {
            float xr[16];
            if (tid < 32) {
                #pragma unroll
                for (int i = 0; i < 16; i++) xr[i] = sKQ[(r0+i)*36 + tid];
            } else {
                const int cc = tid - 32;
                #pragma unroll
                for (int i = 0; i < 16; i++) xr[i] = sV[(r0+i)*64 + cc];
            }
            #pragma unroll
            for (int i = 1; i < 16; i++) {
                const float* Lr = sL + (r0+i)*68 + r0;
                #pragma unroll
                for (int j = 0; j < i; j++)
                    xr[i] = fmaf(-Lr[j], xr[j], xr[i]);
            }
            if (tid < 32) {
                #pragma unroll
                for (int i = 1; i < 16; i++) sKQ[(r0+i)*36 + tid] = xr[i];
            } else {
                const int cc = tid - 32;
                #pragma unroll
                for (int i = 1; i < 16; i++) sV[(r0+i)*64 + cc] = xr[i];
            }
        }
        __syncthreads();
    }
    // w in sKQ, u in sV

    // ---- fused P|C = e * (kdR^T @ [w|u]) via tf32x3 mma ----
    {
        const int wm = warp >> 2, wn = warp & 3;
        const int m0p = wm << 4;
        float pc[3][4];
        #pragma unroll
        for (int nt = 0; nt < 3; nt++)
            #pragma unroll
            for (int r = 0; r < 4; r++) pc[nt][r] = 0.f;
        #pragma unroll 2
        for (int kt = 0; kt < 8; kt++) {
            const int k0 = kt << 3;
            unsigned ahi[4], alo[4];
            {
                float v0 = sKD[(k0+tg)*36   + m0p + gid];
                float v1 = sKD[(k0+tg)*36   + m0p + gid + 8];
                float v2 = sKD[(k0+tg+4)*36 + m0p + gid];
                float v3 = sKD[(k0+tg+4)*36 + m0p + gid + 8];
                split_tf(v0, ahi[0], alo[0]); split_tf(v1, ahi[1], alo[1]);
                split_tf(v2, ahi[2], alo[2]); split_tf(v3, ahi[3], alo[3]);
            }
            #pragma unroll
            for (int nt = 0; nt < 3; nt++) {
                const int ncol = wn*24 + nt*8;
                const float* xb; int ld, off;
                if (ncol < 32) { xb = sKQ; ld = 36; off = ncol; }
                else           { xb = sV;  ld = 64; off = ncol - 32; }
                unsigned bhi[2], blo[2];
                loadB_kn(xb, ld, k0 + tg, off + gid, bhi, blo);
                mma3(pc[nt], ahi, alo, bhi, blo);
            }
        }
        #pragma unroll
        for (int nt = 0; nt < 3; nt++) {
            const int ncol = wn*24 + nt*8 + 2*tg;
            const int r0i = m0p + gid, r1i = m0p + gid + 8;
            float e0 = sE[r0i], e1 = sE[r1i];
            if (ncol < 32) {
                *(float2*)(g_P + (size_t)cid*1024 + r0i*32 + ncol) =
                    make_float2(e0*pc[nt][0], e0*pc[nt][1]);
                *(float2*)(g_P + (size_t)cid*1024 + r1i*32 + ncol) =
                    make_float2(e1*pc[nt][2], e1*pc[nt][3]);
            } else {
                *(float2*)(g_C + (size_t)cid*2048 + r0i*64 + (ncol-32)) =
                    make_float2(e0*pc[nt][0], e0*pc[nt][1]);
                *(float2*)(g_C + (size_t)cid*2048 + r1i*64 + (ncol-32)) =
                    make_float2(e1*pc[nt][2], e1*pc[nt][3]);
            }
        }
    }
    if (tid < KD) g_E[cid*KD + tid] = sE[tid];

    // ---- store w, u, kdR ----
    for (int idx = tid; idx < 512; idx += 256) {
        int i = idx >> 3, c4 = (idx & 7) << 2;
        *(float4*)(g_W + (size_t)cid*2048 + i*32 + c4) =
            *(const float4*)(sKQ + i*36 + c4);
    }
    for (int idx = tid; idx < 1024; idx += 256) {
        int i = idx >> 4, c4 = (idx & 15) << 2;
        *(float4*)(g_U + (size_t)cid*4096 + i*64 + c4) =
            *(const float4*)(sV + i*64 + c4);
    }
    for (int idx = tid; idx < 512; idx += 256) {
        int i = idx >> 3, c4 = (idx & 7) << 2;
        *(float4*)(g_KD + (size_t)cid*2048 + i*32 + c4) =
            *(const float4*)(sKD + i*36 + c4);
    }
}

// ===========================================================================
// Phase 2: S_{t+1} = diag(e)S - P S + C.  1 warp per (pair, 8-col slice).
// ===========================================================================
#define P4C(arr, m) ( ((m)&3)==0 ? arr[(m)>>2].x : ((m)&3)==1 ? arr[(m)>>2].y \
                    : ((m)&3)==2 ? arr[(m)>>2].z : arr[(m)>>2].w )

__global__ void __launch_bounds__(32) phase2_kernel()
{
    const int p     = blockIdx.x >> 3;
    const int vbase = (blockIdx.x & 7) << 3;
    const int lane  = threadIdx.x;
    const size_t base = (size_t)p*128;

    float4 Pc[8], Pn[8], Cc[2], Cn[2];
    float  ec, en;
    float  s[8];
    #pragma unroll
    for (int j = 0; j < 8; j++) s[j] = 0.f;

    {
        const float4* Pp = (const float4*)(g_P + base*1024 + lane*32);
        #pragma unroll
        for (int r = 0; r < 8; r++) Pc[r] = Pp[r];
        const float4* Cp = (const float4*)(g_C + base*2048 + lane*64 + vbase);
        Cc[0] = Cp[0]; Cc[1] = Cp[1];
        ec = g_E[base*32 + lane];
    }

    #pragma unroll 1
    for (int t = 0; t < 128; t++) {
        const size_t cid = base + t;
        if (t + 1 < 128) {
            const size_t cid1 = cid + 1;
            const float4* Pp = (const float4*)(g_P + cid1*1024 + lane*32);
            #pragma unroll
            for (int r = 0; r < 8; r++) Pn[r] = Pp[r];
            const float4* Cp = (const float4*)(g_C + cid1*2048 + lane*64 + vbase);
            Cn[0] = Cp[0]; Cn[1] = Cp[1];
            en = g_E[cid1*32 + lane];
        }
        float4* Sp = (float4*)(g_S + cid*2048 + lane*64 + vbase);
        Sp[0] = make_float4(s[0], s[1], s[2], s[3]);
        Sp[1] = make_float4(s[4], s[5], s[6], s[7]);

        float acc[8];
        acc[0]=fmaf(ec,s[0],Cc[0].x); acc[1]=fmaf(ec,s[1],Cc[0].y);
        acc[2]=fmaf(ec,s[2],Cc[0].z); acc[3]=fmaf(ec,s[3],Cc[0].w);
        acc[4]=fmaf(ec,s[4],Cc[1].x); acc[5]=fmaf(ec,s[5],Cc[1].y);
        acc[6]=fmaf(ec,s[6],Cc[1].z); acc[7]=fmaf(ec,s[7],Cc[1].w);

        #pragma unroll
        for (int m = 0; m < 32; m++) {
            float pm = P4C(Pc, m);
            #pragma unroll
            for (int j = 0; j < 8; j++)
                acc[j] = fmaf(-pm, __shfl_sync(0xffffffffu, s[j], m), acc[j]);
        }
        #pragma unroll
        for (int j = 0; j < 8; j++) s[j] = acc[j];
        #pragma unroll
        for (int r = 0; r < 8; r++) Pc[r] = Pn[r];
        Cc[0] = Cn[0]; Cc[1] = Cn[1];
        ec = en;
    }
}

// ===========================================================================
// Phase 3: o = qg S + Aqk (u - w S) — all GEMMs via tf32x3 mma
// ===========================================================================
__global__ void __launch_bounds__(256, 4) phase3_kernel(float* __restrict__ out)
{
    extern __shared__ float sm[];
    float* sA  = sm + P3_A;     // Aqk [64][68]
    float* sKD = sm + P3_KD2;   // kdR [64][36]
    float* sS  = sm + P3_KD2;   // S [32][72] (overlays kdR after GEMM1)
    float* sWQ = sm + P3_WQ;    // qg then w [64][36]
    float* sVn = sm + P3_VN;    // u -> v_new [64][72]

    const int cid  = blockIdx.x;
    const int pair = cid >> 7, c = cid & 127;
    const int b    = pair >> 4, h = pair & 15;
    const int t0   = c * BT_;
    const int tid  = threadIdx.x;
    const int warp = tid >> 5, lane = tid & 31;
    const int gid  = lane >> 2, tg = lane & 3;
    const int m0   = (warp >> 1) << 4;
    const int n0   = (warp & 1) << 5;

    // ---- load qg, kdR, u ----
    for (int idx = tid; idx < 512; idx += 256) {
        int i = idx >> 3, c4 = (idx & 7) << 2;
        *(float4*)(sWQ + i*36 + c4) =
            *(const float4*)(g_QG + (size_t)cid*2048 + i*32 + c4);
    }
    for (int idx = tid; idx < 512; idx += 256) {
        int i = idx >> 3, c4 = (idx & 7) << 2;
        *(float4*)(sKD + i*36 + c4) =
            *(const float4*)(g_KD + (size_t)cid*2048 + i*32 + c4);
    }
    for (int idx = tid; idx < 1024; idx += 256) {
        int i = idx >> 4, c4 = (idx & 15) << 2;
        *(float4*)(sVn + i*72 + c4) =
            *(const float4*)(g_U + (size_t)cid*4096 + i*64 + c4);
    }
    __syncthreads();

    // ---- GEMM1: Aqk = qg @ kdR^T -> sA (lower tiles only) ----
    if (n0 <= m0 + 15) {
        float aq[4][4];
        #pragma unroll
        for (int nt = 0; nt < 4; nt++)
            #pragma unroll
            for (int r = 0; r < 4; r++) aq[nt][r] = 0.f;
        #pragma unroll
        for (int kt = 0; kt < 4; kt++) {
            const int k0 = kt << 3;
            unsigned ahi[4], alo[4];
            loadA_frag(sWQ, 36, m0 + gid, k0 + tg, ahi, alo, 1.f);
            #pragma unroll
            for (int nt = 0; nt < 4; nt++) {
                if (n0 + nt*8 <= m0 + 15) {
                    unsigned bhi[2], blo[2];
                    loadB_nt(sKD, 36, n0 + nt*8 + gid, k0 + tg, bhi, blo);
                    mma3(aq[nt], ahi, alo, bhi, blo);
                }
            }
        }
        #pragma unroll
        for (int nt = 0; nt < 4; nt++) {
            if (n0 + nt*8 <= m0 + 15) {
                const int cb = n0 + nt*8 + 2*tg;
                sA[(m0+gid)*68 + cb]       = aq[nt][0];
                sA[(m0+gid)*68 + cb + 1]   = aq[nt][1];
                sA[(m0+gid+8)*68 + cb]     = aq[nt][2];
                sA[(m0+gid+8)*68 + cb + 1] = aq[nt][3];
            }
        }
    }
    __syncthreads();   // kdR dead; Aqk visible

    // ---- load S over kdR region [32][72] ----
    for (int idx = tid; idx < 512; idx += 256) {
        int kk = idx >> 4, c4 = (idx & 15) << 2;
        *(float4*)(sS + kk*72 + c4) =
            *(const float4*)(g_S + (size_t)cid*2048 + kk*64 + c4);
    }
    __syncthreads();

    // ---- GEMM2: oacc = qg @ S ----
    float oac[4][4];
    #pragma unroll
    for (int nt = 0; nt < 4; nt++)
        #pragma unroll
        for (int r = 0; r < 4; r++) oac[nt][r] = 0.f;
    #pragma unroll
    for (int kt = 0; kt < 4; kt++) {
        const int k0 = kt << 3;
        unsigned ahi[4], alo[4];
        loadA_frag(sWQ, 36, m0 + gid, k0 + tg, ahi, alo, 1.f);
        #pragma unroll
        for (int nt = 0; nt < 4; nt++) {
            unsigned bhi[2], blo[2];
            loadB_kn(sS, 72, k0 + tg, n0 + nt*8 + gid, bhi, blo);
            mma3(oac[nt], ahi, alo, bhi, blo);
        }
    }
    __syncthreads();   // qg dead

    // ---- load w over qg ----
    for (int idx = tid; idx < 512; idx += 256) {
        int i = idx >> 3, c4 = (idx & 7) << 2;
        *(float4*)(sWQ + i*36 + c4) =
            *(const float4*)(g_W + (size_t)cid*2048 + i*32 + c4);
    }
    __syncthreads();

    // ---- GEMM3: v_new = u + (-w) @ S, RMW into sVn ----
    {
        float ws[4][4];
        #pragma unroll
        for (int nt = 0; nt < 4; nt++)
            #pragma unroll
            for (int r = 0; r < 4; r++) ws[nt][r] = 0.f;
        #pragma unroll
        for (int kt = 0; kt < 4; kt++) {
            const int k0 = kt << 3;
            unsigned ahi[4], alo[4];
            loadA_frag(sWQ, 36, m0 + gid, k0 + tg, ahi, alo, -1.f);
            #pragma unroll
            for (int nt = 0; nt < 4; nt++) {
                unsigned bhi[2], blo[2];
                loadB_kn(sS, 72, k0 + tg, n0 + nt*8 + gid, bhi, blo);
                mma3(ws[nt], ahi, alo, bhi, blo);
            }
        }
        #pragma unroll
        for (int nt = 0; nt < 4; nt++) {
            const int cb = n0 + nt*8 + 2*tg;
            sVn[(m0+gid)*72 + cb]       += ws[nt][0];
            sVn[(m0+gid)*72 + cb + 1]   += ws[nt][1];
            sVn[(m0+gid+8)*72 + cb]     += ws[nt][2];
            sVn[(m0+gid+8)*72 + cb + 1] += ws[nt][3];
        }
    }
    __syncthreads();

    // ---- GEMM5: oacc += tril(Aqk) @ v_new ----
    {
        const int ktmax = (m0 + 15) >> 3;   // 1,3,5,7 per warpM
        #pragma unroll 2
        for (int kt = 0; kt <= ktmax; kt++) {
            const int k0 = kt << 3;
            const int r0i = m0 + gid, r1i = m0 + gid + 8;
            float v0 = (k0 + tg     <= r0i) ? sA[r0i*68 + k0 + tg]     : 0.f;
            float v1 = (k0 + tg     <= r1i) ? sA[r1i*68 + k0 + tg]     : 0.f;
            float v2 = (k0 + tg + 4 <= r0i) ? sA[r0i*68 + k0 + tg + 4] : 0.f;
            float v3 = (k0 + tg + 4 <= r1i) ? sA[r1i*68 + k0 + tg + 4] : 0.f;
            unsigned ahi[4], alo[4];
            split_tf(v0, ahi[0], alo[0]); split_tf(v1, ahi[1], alo[1]);
            split_tf(v2, ahi[2], alo[2]); split_tf(v3, ahi[3], alo[3]);
            #pragma unroll
            for (int nt = 0; nt < 4; nt++) {
                unsigned bhi[2], blo[2];
                loadB_kn(sVn, 72, k0 + tg, n0 + nt*8 + gid, bhi, blo);
                mma3(oac[nt], ahi, alo, bhi, blo);
            }
        }
    }

    // ---- store out from c-fragments ----
    #pragma unroll
    for (int nt = 0; nt < 4; nt++) {
        const int cb = n0 + nt*8 + 2*tg;
        const size_t r0o = (((size_t)(b*T_ + t0 + m0 + gid)*H_ + h) << 6);
        const size_t r1o = (((size_t)(b*T_ + t0 + m0 + gid + 8)*H_ + h) << 6);
        out[r0o + cb]     = oac[nt][0];
        out[r0o + cb + 1] = oac[nt][1];
        out[r1o + cb]     = oac[nt][2];
        out[r1o + cb + 1] = oac[nt][3];
    }
}

// ===========================================================================
extern "C" void kernel_launch(void* const* d_in, const int* in_sizes, int n_in,
                              void* d_out, int out_size)
{
    const float* q       = (const float*)d_in[0];
    const float* k       = (const float*)d_in[1];
    const float* v       = (const float*)d_in[2];
    const float* graw    = (const float*)d_in[3];
    const float* beta    = (const float*)d_in[4];
    const float* A_log   = (const float*)d_in[5];
    const float* dt_bias = (const float*)d_in[6];
    float* out = (float*)d_out;

    cudaFuncSetAttribute(phase1_kernel,
        cudaFuncAttributeMaxDynamicSharedMemorySize, P1_BYTES);
    cudaFuncSetAttribute(phase3_kernel,
        cudaFuncAttributeMaxDynamicSharedMemorySize, P3_BYTES);

    phase1_kernel<<<NCHUNK, 256, P1_BYTES>>>(q, k, v, graw, beta, A_log, dt_bias);
    phase2_kernel<<<256, 32>>>();
    phase3_kernel<<<NCHUNK, 256, P3_BYTES>>>(out);
}

// round 13
// speedup vs baseline: 1.1992x; 1.0595x over previous
#include <cuda_runtime.h>
#include <cuda_bf16.h>
#include <math.h>

#define B_   2
#define T_   8192
#define H_   16
#define KD   32
#define VD   64
#define BT_  64
#define NT_  128
#define NCHUNK 4096   // B*H*NT

typedef unsigned long long ull;

// ---------------- tf32x3 mma helpers (m16n8k8) ----------------
__device__ __forceinline__ void split_tf(float x, unsigned& hi, unsigned& lo) {
    hi = __float_as_uint(x) & 0xFFFFE000u;
    lo = __float_as_uint(x - __uint_as_float(hi));
}
__device__ __forceinline__ void mma_m16n8k8(float c[4], const unsigned a[4], const unsigned b[2]) {
    asm volatile("mma.sync.aligned.m16n8k8.row.col.f32.tf32.tf32.f32 "
        "{%0,%1,%2,%3}, {%4,%5,%6,%7}, {%8,%9}, {%0,%1,%2,%3};"
        : "+f"(c[0]), "+f"(c[1]), "+f"(c[2]), "+f"(c[3])
        : "r"(a[0]), "r"(a[1]), "r"(a[2]), "r"(a[3]), "r"(b[0]), "r"(b[1]));
}
__device__ __forceinline__ void mma3(float c[4], const unsigned ahi[4], const unsigned alo[4],
                                     const unsigned bhi[2], const unsigned blo[2]) {
    mma_m16n8k8(c, ahi, bhi);
    mma_m16n8k8(c, ahi, blo);
    mma_m16n8k8(c, alo, bhi);
}
__device__ __forceinline__ void loadA_frag(const float* A, int ld, int row, int col,
                                           unsigned hi[4], unsigned lo[4], float sgn) {
    float v0 = sgn * A[row*ld + col];
    float v1 = sgn * A[(row+8)*ld + col];
    float v2 = sgn * A[row*ld + col + 4];
    float v3 = sgn * A[(row+8)*ld + col + 4];
    split_tf(v0, hi[0], lo[0]); split_tf(v1, hi[1], lo[1]);
    split_tf(v2, hi[2], lo[2]); split_tf(v3, hi[3], lo[3]);
}
__device__ __forceinline__ void loadB_nt(const float* Bm, int ld, int nrow, int kcol,
                                         unsigned hi[2], unsigned lo[2]) {
    split_tf(Bm[nrow*ld + kcol],     hi[0], lo[0]);
    split_tf(Bm[nrow*ld + kcol + 4], hi[1], lo[1]);
}
__device__ __forceinline__ void loadB_kn(const float* Bm, int ld, int krow, int ncol,
                                         unsigned hi[2], unsigned lo[2]) {
    split_tf(Bm[krow*ld + ncol],       hi[0], lo[0]);
    split_tf(Bm[(krow+4)*ld + ncol],   hi[1], lo[1]);
}
__device__ __forceinline__ float softplus_fast(float x) {
    return fmaxf(x, 0.f) + __logf(1.0f + __expf(-fabsf(x)));
}
// ---------------- cp.async helpers ----------------
__device__ __forceinline__ unsigned smem_u32(const void* p) {
    return (unsigned)__cvta_generic_to_shared(p);
}
__device__ __forceinline__ void cp16(unsigned dst, const void* src) {
    asm volatile("cp.async.cg.shared.global [%0], [%1], 16;" :: "r"(dst), "l"(src));
}
#define CP_COMMIT() asm volatile("cp.async.commit_group;" ::: "memory")
#define CP_WAIT(N)  asm volatile("cp.async.wait_group %0;" :: "n"(N) : "memory")

// ------------------- device scratch (no allocation allowed) ---------------
__device__ float g_P [NCHUNK*KD*KD];
__device__ float g_C [NCHUNK*KD*VD];
__device__ float g_E [NCHUNK*KD];
__device__ float g_W [NCHUNK*BT_*KD];
__device__ float g_U [(size_t)NCHUNK*BT_*VD];
__device__ float g_QG[NCHUNK*BT_*KD];
__device__ float g_KD[NCHUNK*BT_*KD];           // kdR row-major [64][32]
__device__ float g_S [(size_t)NCHUNK*KD*VD];

// ---------------- phase-1 smem layout (floats) ----------------
#define P1_KQ   0        // b*kg [64][36]
#define P1_KD   2304     // kdR  [64][36]
#define P1_V    4608     // b*v [64][64]; gcum overlays [64][32]
#define P1_L    8704     // L [64][68]
#define P1_B    13056    // beta [64]
#define P1_E    13120    // e [32]
#define P1_BS   13152    // block sums [8][32]
#define P1_FLOATS 13408
#define P1_BYTES  (P1_FLOATS*4)      // 53632

// ---------------- phase-3 smem layout (floats), no overlays ----------------
#define P3_A    0        // Aqk [64][68]            4352
#define P3_KD2  4352     // kdR [64][36]            2304
#define P3_QG   6656     // qg  [64][36]            2304
#define P3_W    8960     // w   [64][36]            2304
#define P3_S    11264    // S   [32][72]            2304
#define P3_VN   13568    // u -> v_new [64][72]     4608
#define P3_FLOATS 18176
#define P3_BYTES  (P3_FLOATS*4)      // 72704 -> 3 CTAs/SM

// ===========================================================================
__global__ void __launch_bounds__(256, 4) phase1_kernel(
    const float* __restrict__ q, const float* __restrict__ k,
    const float* __restrict__ v, const float* __restrict__ graw,
    const float* __restrict__ beta, const float* __restrict__ A_log,
    const float* __restrict__ dt_bias)
{
    extern __shared__ float sm[];
    float* sKQ = sm + P1_KQ;    // stride 36
    float* sKD = sm + P1_KD;    // stride 36
    float* sV  = sm + P1_V;     // stride 64
    float* sG  = sm + P1_V;     // overlay [64][32]
    float* sL  = sm + P1_L;     // stride 68
    float* sB  = sm + P1_B;
    float* sE  = sm + P1_E;
    float* sBS = sm + P1_BS;

    const int cid  = blockIdx.x;
    const int pair = cid >> 7, c = cid & 127;
    const int b    = pair >> 4, h = pair & 15;
    const int t0   = c * BT_;
    const int tid  = threadIdx.x;
    const int warp = tid >> 5, lane = tid & 31;
    const int gid  = lane >> 2, tg = lane & 3;
    const int m0   = (warp >> 1) << 4;
    const int n0   = (warp & 1) << 5;

    const float expA = __expf(A_log[h]);

    // ---- gate ----
    for (int idx = tid; idx < 512; idx += 256) {
        int i = idx >> 3, q4 = (idx & 7) << 2;
        float4 gr = *(const float4*)(graw + (((size_t)(b*T_ + t0 + i)*H_ + h) << 5) + q4);
        float4 db = *(const float4*)(dt_bias + h*KD + q4);
        float4 o;
        o.x = -expA * softplus_fast(gr.x + db.x);
        o.y = -expA * softplus_fast(gr.y + db.y);
        o.z = -expA * softplus_fast(gr.z + db.z);
        o.w = -expA * softplus_fast(gr.w + db.w);
        *(float4*)(sG + i*KD + q4) = o;
    }
    for (int i = tid; i < BT_; i += 256)
        sB[i] = beta[(size_t)(b*T_ + t0 + i)*H_ + h];
    __syncthreads();

    // ---- parallel cumsum ----
    {
        const int blk = tid >> 5, kk = tid & 31;
        float pref[8];
        float run = 0.f;
        #pragma unroll
        for (int t = 0; t < 8; t++) {
            run += sG[(blk*8 + t)*KD + kk];
            pref[t] = run;
        }
        sBS[blk*32 + kk] = run;
        __syncthreads();
        float pre = 0.f;
        #pragma unroll
        for (int j = 0; j < 7; j++)
            if (j < blk) pre += sBS[j*32 + kk];
        #pragma unroll
        for (int t = 0; t < 8; t++)
            sG[(blk*8 + t)*KD + kk] = fmaxf(pre + pref[t], -80.f);
        if (blk == 7) sE[kk] = __expf(fmaxf(pre + pref[7], -80.f));
    }
    __syncthreads();

    // ---- k,q rows: b*kg -> sKQ, kdR -> sKD, qg -> g_QG ----
    for (int r = warp; r < BT_; r += 8) {
        float gc = sG[r*KD + lane];
        float eg = __expf(gc);

        float kv = k[((size_t)((b*T_+t0+r)*H_ + h) << 5) + lane];
        float ss = kv*kv;
        #pragma unroll
        for (int o = 16; o; o >>= 1) ss += __shfl_xor_sync(0xffffffffu, ss, o);
        float kn = kv * rsqrtf(fmaxf(ss, 1e-12f));
        sKQ[r*36 + lane] = sB[r] * kn * eg;
        sKD[r*36 + lane] = kn * __expf(-gc);

        float qv = q[((size_t)((b*T_+t0+r)*H_+h) << 5) + lane];
        float qs = qv*qv;
        #pragma unroll
        for (int o = 16; o; o >>= 1) qs += __shfl_xor_sync(0xffffffffu, qs, o);
        float qn = 0.1767766952966369f * qv * rsqrtf(fmaxf(qs, 1e-12f));
        g_QG[(size_t)cid*2048 + r*KD + lane] = qn * eg;
    }
    __syncthreads();   // sG dead

    // ---- b*v -> sV ----
    for (int idx = tid; idx < 1024; idx += 256) {
        int i = idx >> 4, c4 = (idx & 15) << 2;
        float4 vv = *(const float4*)(v + (((size_t)(b*T_+t0+i)*H_+h) << 6) + c4);
        float bi = sB[i];
        vv.x *= bi; vv.y *= bi; vv.z *= bi; vv.w *= bi;
        *(float4*)(sV + i*64 + c4) = vv;
    }

    // ---- L = (b*kg) @ kdR^T via tf32x3 mma (lower tiles only) ----
    if (n0 <= m0 + 15) {
        float lac[4][4];
        #pragma unroll
        for (int nt = 0; nt < 4; nt++)
            #pragma unroll
            for (int r = 0; r < 4; r++) lac[nt][r] = 0.f;
        #pragma unroll
        for (int kt = 0; kt < 4; kt++) {
            const int k0 = kt << 3;
            unsigned ahi[4], alo[4];
            loadA_frag(sKQ, 36, m0 + gid, k0 + tg, ahi, alo, 1.f);
            #pragma unroll
            for (int nt = 0; nt < 4; nt++) {
                if (n0 + nt*8 <= m0 + 15) {
                    unsigned bhi[2], blo[2];
                    loadB_nt(sKD, 36, n0 + nt*8 + gid, k0 + tg, bhi, blo);
                    mma3(lac[nt], ahi, alo, bhi, blo);
                }
            }
        }
        #pragma unroll
        for (int nt = 0; nt < 4; nt++) {
            if (n0 + nt*8 <= m0 + 15) {
                const int cb = n0 + nt*8 + 2*tg;
                sL[(m0+gid)*68 + cb]       = lac[nt][0];
                sL[(m0+gid)*68 + cb + 1]   = lac[nt][1];
                sL[(m0+gid+8)*68 + cb]     = lac[nt][2];
                sL[(m0+gid+8)*68 + cb + 1] = lac[nt][3];
            }
        }
    }
    __syncthreads();

    // ---- blocked forward substitution on x = [sKQ(36) | sV(64)] ----
    #pragma unroll 1
    for (int blk = 0; blk < 4; ++blk) {
        const int r0 = blk << 4;
        if (blk) {
            if (warp < 6) {
                const int n0w = warp << 4;
                const int ktn = blk << 1;
                float up[2][4];
                #pragma unroll
                for (int nt = 0; nt < 2; nt++)
                    #pragma unroll
                    for (int r = 0; r < 4; r++) up[nt][r] = 0.f;
                #pragma unroll 2
                for (int kt = 0; kt < ktn; kt++) {
                    const int k0 = kt << 3;
                    unsigned ahi[4], alo[4];
                    loadA_frag(sL, 68, r0 + gid, k0 + tg, ahi, alo, -1.f);
                    #pragma unroll
                    for (int nt = 0; nt < 2; nt++) {
                        const int ncol = n0w + nt*8;
                        const float* xb; int ld, off;
                        if (ncol < 32) { xb = sKQ; ld = 36; off = ncol; }
                        else           { xb = sV;  ld = 64; off = ncol - 32; }
                        unsigned bhi[2], blo[2];
                        loadB_kn(xb, ld, k0 + tg, off + gid, bhi, blo);
                        mma3(up[nt], ahi, alo, bhi, blo);
                    }
                }
                #pragma unroll
                for (int nt = 0; nt < 2; nt++) {
                    const int ncol = n0w + nt*8 + 2*tg;
                    float* xb; int ld, off;
                    if (ncol < 32) { xb = sKQ; ld = 36; off = ncol; }
                    else           { xb = sV;  ld = 64; off = ncol - 32; }
                    xb[(r0+gid)*ld + off]       += up[nt][0];
                    xb[(r0+gid)*ld + off + 1]   += up[nt][1];
                    xb[(r0+gid+8)*ld + off]     += up[nt][2];
                    xb[(r0+gid+8)*ld + off + 1] += up[nt][3];
                }
            }
            __syncthreads();
        }
        if (tid < 96) {
            float xr[16];
            if (tid < 32) {
                #pragma unroll
                for (int i = 0; i < 16; i++) xr[i] = sKQ[(r0+i)*36 + tid];
            } else {
                const int cc = tid - 32;
                #pragma unroll
                for (int i = 0; i < 16; i++) xr[i] = sV[(r0+i)*64 + cc];
            }
            #pragma unroll
            for (int i = 1; i < 16; i++) {
                const float* Lr = sL + (r0+i)*68 + r0;
                #pragma unroll
                for (int j = 0; j < i; j++)
                    xr[i] = fmaf(-Lr[j], xr[j], xr[i]);
            }
            if (tid < 32) {
                #pragma unroll
                for (int i = 1; i < 16; i++) sKQ[(r0+i)*36 + tid] = xr[i];
            } else {
                const int cc = tid - 32;
                #pragma unroll
                for (int i = 1; i < 16; i++) sV[(r0+i)*64 + cc] = xr[i];
            }
        }
        __syncthreads();
    }
    // w in sKQ, u in sV

    // ---- fused P|C = e * (kdR^T @ [w|u]) via tf32x3 mma ----
    {
        const int wm = warp >> 2, wn = warp & 3;
        const int m0p = wm << 4;
        float pc[3][4];
        #pragma unroll
        for (int nt = 0; nt < 3; nt++)
            #pragma unroll
            for (int r = 0; r < 4; r++) pc[nt][r] = 0.f;
        #pragma unroll 2
        for (int kt = 0; kt < 8; kt++) {
            const int k0 = kt << 3;
            unsigned ahi[4], alo[4];
            {
                float v0 = sKD[(k0+tg)*36   + m0p + gid];
                float v1 = sKD[(k0+tg)*36   + m0p + gid + 8];
                float v2 = sKD[(k0+tg+4)*36 + m0p + gid];
                float v3 = sKD[(k0+tg+4)*36 + m0p + gid + 8];
                split_tf(v0, ahi[0], alo[0]); split_tf(v1, ahi[1], alo[1]);
                split_tf(v2, ahi[2], alo[2]); split_tf(v3, ahi[3], alo[3]);
            }
            #pragma unroll
            for (int nt = 0; nt < 3; nt++) {
                const int ncol = wn*24 + nt*8;
                const float* xb; int ld, off;
                if (ncol < 32) { xb = sKQ; ld = 36; off = ncol; }
                else           { xb = sV;  ld = 64; off = ncol - 32; }
                unsigned bhi[2], blo[2];
                loadB_kn(xb, ld, k0 + tg, off + gid, bhi, blo);
                mma3(pc[nt], ahi, alo, bhi, blo);
            }
        }
        #pragma unroll
        for (int nt = 0; nt < 3; nt++) {
            const int ncol = wn*24 + nt*8 + 2*tg;
            const int r0i = m0p + gid, r1i = m0p + gid + 8;
            float e0 = sE[r0i], e1 = sE[r1i];
            if (ncol < 32) {
                *(float2*)(g_P + (size_t)cid*1024 + r0i*32 + ncol) =
                    make_float2(e0*pc[nt][0], e0*pc[nt][1]);
                *(float2*)(g_P + (size_t)cid*1024 + r1i*32 + ncol) =
                    make_float2(e1*pc[nt][2], e1*pc[nt][3]);
            } else {
                *(float2*)(g_C + (size_t)cid*2048 + r0i*64 + (ncol-32)) =
                    make_float2(e0*pc[nt][0], e0*pc[nt][1]);
                *(float2*)(g_C + (size_t)cid*2048 + r1i*64 + (ncol-32)) =
                    make_float2(e1*pc[nt][2], e1*pc[nt][3]);
            }
        }
    }
    if (tid < KD) g_E[cid*KD + tid] = sE[tid];

    // ---- store w, u, kdR ----
    for (int idx = tid; idx < 512; idx += 256) {
        int i = idx >> 3, c4 = (idx & 7) << 2;
        *(float4*)(g_W + (size_t)cid*2048 + i*32 + c4) =
            *(const float4*)(sKQ + i*36 + c4);
    }
    for (int idx = tid; idx < 1024; idx += 256) {
        int i = idx >> 4, c4 = (idx & 15) << 2;
        *(float4*)(g_U + (size_t)cid*4096 + i*64 + c4) =
            *(const float4*)(sV + i*64 + c4);
    }
    for (int idx = tid; idx < 512; idx += 256) {
        int i = idx >> 3, c4 = (idx & 7) << 2;
        *(float4*)(g_KD + (size_t)cid*2048 + i*32 + c4) =
            *(const float4*)(sKD + i*36 + c4);
    }
}

// ===========================================================================
// Phase 2: S_{t+1} = diag(e)S - P S + C.  1 warp per (pair, 8-col slice).
// ===========================================================================
#define P4C(arr, m) ( ((m)&3)==0 ? arr[(m)>>2].x : ((m)&3)==1 ? arr[(m)>>2].y \
                    : ((m)&3)==2 ? arr[(m)>>2].z : arr[(m)>>2].w )

__global__ void __launch_bounds__(32) phase2_kernel()
{
    const int p     = blockIdx.x >> 3;
    const int vbase = (blockIdx.x & 7) << 3;
    const int lane  = threadIdx.x;
    const size_t base = (size_t)p*128;

    float4 Pc[8], Pn[8], Cc[2], Cn[2];
    float  ec, en;
    float  s[8];
    #pragma unroll
    for (int j = 0; j < 8; j++) s[j] = 0.f;

    {
        const float4* Pp = (const float4*)(g_P + base*1024 + lane*32);
        #pragma unroll
        for (int r = 0; r < 8; r++) Pc[r] = Pp[r];
        const float4* Cp = (const float4*)(g_C + base*2048 + lane*64 + vbase);
        Cc[0] = Cp[0]; Cc[1] = Cp[1];
        ec = g_E[base*32 + lane];
    }

    #pragma unroll 1
    for (int t = 0; t < 128; t++) {
        const size_t cid = base + t;
        if (t + 1 < 128) {
            const size_t cid1 = cid + 1;
            const float4* Pp = (const float4*)(g_P + cid1*1024 + lane*32);
            #pragma unroll
            for (int r = 0; r < 8; r++) Pn[r] = Pp[r];
            const float4* Cp = (const float4*)(g_C + cid1*2048 + lane*64 + vbase);
            Cn[0] = Cp[0]; Cn[1] = Cp[1];
            en = g_E[cid1*32 + lane];
        }
        float4* Sp = (float4*)(g_S + cid*2048 + lane*64 + vbase);
        Sp[0] = make_float4(s[0], s[1], s[2], s[3]);
        Sp[1] = make_float4(s[4], s[5], s[6], s[7]);

        float acc[8];
        acc[0]=fmaf(ec,s[0],Cc[0].x); acc[1]=fmaf(ec,s[1],Cc[0].y);
        acc[2]=fmaf(ec,s[2],Cc[0].z); acc[3]=fmaf(ec,s[3],Cc[0].w);
        acc[4]=fmaf(ec,s[4],Cc[1].x); acc[5]=fmaf(ec,s[5],Cc[1].y);
        acc[6]=fmaf(ec,s[6],Cc[1].z); acc[7]=fmaf(ec,s[7],Cc[1].w);

        #pragma unroll
        for (int m = 0; m < 32; m++) {
            float pm = P4C(Pc, m);
            #pragma unroll
            for (int j = 0; j < 8; j++)
                acc[j] = fmaf(-pm, __shfl_sync(0xffffffffu, s[j], m), acc[j]);
        }
        #pragma unroll
        for (int j = 0; j < 8; j++) s[j] = acc[j];
        #pragma unroll
        for (int r = 0; r < 8; r++) Pc[r] = Pn[r];
        Cc[0] = Cn[0]; Cc[1] = Cn[1];
        ec = en;
    }
}

// ===========================================================================
// Phase 3: o = qg S + Aqk (u - w S) — tf32x3 mma + cp.async prefetch pipeline
// ===========================================================================
__global__ void __launch_bounds__(256, 3) phase3_kernel(float* __restrict__ out)
{
    extern __shared__ float sm[];
    float* sA  = sm + P3_A;     // Aqk [64][68]
    float* sKD = sm + P3_KD2;   // kdR [64][36]
    float* sQG = sm + P3_QG;    // qg  [64][36]
    float* sW  = sm + P3_W;     // w   [64][36]
    float* sS  = sm + P3_S;     // S   [32][72]
    float* sVn = sm + P3_VN;    // u -> v_new [64][72]

    const int cid  = blockIdx.x;
    const int pair = cid >> 7, c = cid & 127;
    const int b    = pair >> 4, h = pair & 15;
    const int t0   = c * BT_;
    const int tid  = threadIdx.x;
    const int warp = tid >> 5, lane = tid & 31;
    const int gid  = lane >> 2, tg = lane & 3;
    const int m0   = (warp >> 1) << 4;
    const int n0   = (warp & 1) << 5;

    // ---- cp.async prefetch: group0 {qg,kd}, group1 {S}, group2 {u,w} ----
    {
        // qg, kd (2 x float4 per thread each)
        #pragma unroll
        for (int r = 0; r < 2; r++) {
            int idx = tid + r*256;
            int i = idx >> 3, c4 = (idx & 7) << 2;
            cp16(smem_u32(sQG + i*36 + c4), g_QG + (size_t)cid*2048 + i*32 + c4);
            cp16(smem_u32(sKD + i*36 + c4), g_KD + (size_t)cid*2048 + i*32 + c4);
        }
        CP_COMMIT();
        // S (2 x float4 per thread)
        #pragma unroll
        for (int r = 0; r < 2; r++) {
            int idx = tid + r*256;
            int kk = idx >> 4, c4 = (idx & 15) << 2;
            cp16(smem_u32(sS + kk*72 + c4), g_S + (size_t)cid*2048 + kk*64 + c4);
        }
        CP_COMMIT();
        // u (4 x float4) + w (2 x float4)
        #pragma unroll
        for (int r = 0; r < 4; r++) {
            int idx = tid + r*256;
            int i = idx >> 4, c4 = (idx & 15) << 2;
            cp16(smem_u32(sVn + i*72 + c4), g_U + (size_t)cid*4096 + i*64 + c4);
        }
        #pragma unroll
        for (int r = 0; r < 2; r++) {
            int idx = tid + r*256;
            int i = idx >> 3, c4 = (idx & 7) << 2;
            cp16(smem_u32(sW + i*36 + c4), g_W + (size_t)cid*2048 + i*32 + c4);
        }
        CP_COMMIT();
    }

    // ---- wait group0 (qg,kd) ----
    CP_WAIT(2);
    __syncthreads();

    // ---- GEMM1: Aqk = qg @ kdR^T -> sA (lower tiles only) ----
    if (n0 <= m0 + 15) {
        float aq[4][4];
        #pragma unroll
        for (int nt = 0; nt < 4; nt++)
            #pragma unroll
            for (int r = 0; r < 4; r++) aq[nt][r] = 0.f;
        #pragma unroll
        for (int kt = 0; kt < 4; kt++) {
            const int k0 = kt << 3;
            unsigned ahi[4], alo[4];
            loadA_frag(sQG, 36, m0 + gid, k0 + tg, ahi, alo, 1.f);
            #pragma unroll
            for (int nt = 0; nt < 4; nt++) {
                if (n0 + nt*8 <= m0 + 15) {
                    unsigned bhi[2], blo[2];
                    loadB_nt(sKD, 36, n0 + nt*8 + gid, k0 + tg, bhi, blo);
                    mma3(aq[nt], ahi, alo, bhi, blo);
                }
            }
        }
        #pragma unroll
        for (int nt = 0; nt < 4; nt++) {
            if (n0 + nt*8 <= m0 + 15) {
                const int cb = n0 + nt*8 + 2*tg;
                sA[(m0+gid)*68 + cb]       = aq[nt][0];
                sA[(m0+gid)*68 + cb + 1]   = aq[nt][1];
                sA[(m0+gid+8)*68 + cb]     = aq[nt][2];
                sA[(m0+gid+8)*68 + cb + 1] = aq[nt][3];
            }
        }
    }

    // ---- wait group1 (S) ----
    CP_WAIT(1);
    __syncthreads();

    // ---- GEMM2: oacc = qg @ S ----
    float oac[4][4];
    #pragma unroll
    for (int nt = 0; nt < 4; nt++)
        #pragma unroll
        for (int r = 0; r < 4; r++) oac[nt][r] = 0.f;
    #pragma unroll
    for (int kt = 0; kt < 4; kt++) {
        const int k0 = kt << 3;
        unsigned ahi[4], alo[4];
        loadA_frag(sQG, 36, m0 + gid, k0 + tg, ahi, alo, 1.f);
        #pragma unroll
        for (int nt = 0; nt < 4; nt++) {
            unsigned bhi[2], blo[2];
            loadB_kn(sS, 72, k0 + tg, n0 + nt*8 + gid, bhi, blo);
            mma3(oac[nt], ahi, alo, bhi, blo);
        }
    }

    // ---- wait group2 (u,w) ----
    CP_WAIT(0);
    __syncthreads();

    // ---- GEMM3: v_new = u + (-w) @ S, RMW into sVn ----
    {
        float ws[4][4];
        #pragma unroll
        for (int nt = 0; nt < 4; nt++)
            #pragma unroll
            for (int r = 0; r < 4; r++) ws[nt][r] = 0.f;
        #pragma unroll
        for (int kt = 0; kt < 4; kt++) {
            const int k0 = kt << 3;
            unsigned ahi[4], alo[4];
            loadA_frag(sW, 36, m0 + gid, k0 + tg, ahi, alo, -1.f);
            #pragma unroll
            for (int nt = 0; nt < 4; nt++) {
                unsigned bhi[2], blo[2];
                loadB_kn(sS, 72, k0 + tg, n0 + nt*8 + gid, bhi, blo);
                mma3(ws[nt], ahi, alo, bhi, blo);
            }
        }
        #pragma unroll
        for (int nt = 0; nt < 4; nt++) {
            const int cb = n0 + nt*8 + 2*tg;
            sVn[(m0+gid)*72 + cb]       += ws[nt][0];
            sVn[(m0+gid)*72 + cb + 1]   += ws[nt][1];
            sVn[(m0+gid+8)*72 + cb]     += ws[nt][2];
            sVn[(m0+gid+8)*72 + cb + 1] += ws[nt][3];
        }
    }
    __syncthreads();

    // ---- GEMM5: oacc += tril(Aqk) @ v_new ----
    {
        const int ktmax = (m0 + 15) >> 3;   // 1,3,5,7 per warpM
        #pragma unroll 2
        for (int kt = 0; kt <= ktmax; kt++) {
            const int k0 = kt << 3;
            const int r0i = m0 + gid, r1i = m0 + gid + 8;
            float v0 = (k0 + tg     <= r0i) ? sA[r0i*68 + k0 + tg]     : 0.f;
            float v1 = (k0 + tg     <= r1i) ? sA[r1i*68 + k0 + tg]     : 0.f;
            float v2 = (k0 + tg + 4 <= r0i) ? sA[r0i*68 + k0 + tg + 4] : 0.f;
            float v3 = (k0 + tg + 4 <= r1i) ? sA[r1i*68 + k0 + tg + 4] : 0.f;
            unsigned ahi[4], alo[4];
            split_tf(v0, ahi[0], alo[0]); split_tf(v1, ahi[1], alo[1]);
            split_tf(v2, ahi[2], alo[2]); split_tf(v3, ahi[3], alo[3]);
            #pragma unroll
            for (int nt = 0; nt < 4; nt++) {
                unsigned bhi[2], blo[2];
                loadB_kn(sVn, 72, k0 + tg, n0 + nt*8 + gid, bhi, blo);
                mma3(oac[nt], ahi, alo, bhi, blo);
            }
        }
    }

    // ---- store out from c-fragments ----
    #pragma unroll
    for (int nt = 0; nt < 4; nt++) {
        const int cb = n0 + nt*8 + 2*tg;
        const size_t r0o = (((size_t)(b*T_ + t0 + m0 + gid)*H_ + h) << 6);
        const size_t r1o = (((size_t)(b*T_ + t0 + m0 + gid + 8)*H_ + h) << 6);
        out[r0o + cb]     = oac[nt][0];
        out[r0o + cb + 1] = oac[nt][1];
        out[r1o + cb]     = oac[nt][2];
        out[r1o + cb + 1] = oac[nt][3];
    }
}

// ===========================================================================
extern "C" void kernel_launch(void* const* d_in, const int* in_sizes, int n_in,
                              void* d_out, int out_size)
{
    const float* q       = (const float*)d_in[0];
    const float* k       = (const float*)d_in[1];
    const float* v       = (const float*)d_in[2];
    const float* graw    = (const float*)d_in[3];
    const float* beta    = (const float*)d_in[4];
    const float* A_log   = (const float*)d_in[5];
    const float* dt_bias = (const float*)d_in[6];
    float* out = (float*)d_out;

    cudaFuncSetAttribute(phase1_kernel,
        cudaFuncAttributeMaxDynamicSharedMemorySize, P1_BYTES);
    cudaFuncSetAttribute(phase3_kernel,
        cudaFuncAttributeMaxDynamicSharedMemorySize, P3_BYTES);

    phase1_kernel<<<NCHUNK, 256, P1_BYTES>>>(q, k, v, graw, beta, A_log, dt_bias);
    phase2_kernel<<<256, 32>>>();
    phase3_kernel<<<NCHUNK, 256, P3_BYTES>>>(out);
}